// round 7
// baseline (speedup 1.0000x reference)
#include <cuda_runtime.h>
#include <cuda_bf16.h>
#include <math.h>
#include <stdint.h>

#define BATCH   16
#define SEQ     1024
#define DIM     512
#define NHEAD   16
#define KDIM    32
#define VDIM    128
#define QKVD    192
#define QKV_OUT 3072
#define OUT_DIM 2048
#define MROWS   16384
#define ATT_SCALE 0.17677669529663687f

// ---------------- scratch ----------------
__device__ float         g_qkv [(size_t)MROWS * QKV_OUT];
__device__ float         g_bias[(size_t)NHEAD * SEQ * SEQ];
__device__ __nv_bfloat16 g_xh  [(size_t)MROWS * DIM];
__device__ __nv_bfloat16 g_xl  [(size_t)MROWS * DIM];
__device__ __nv_bfloat16 g_w1h [(size_t)QKV_OUT * DIM];
__device__ __nv_bfloat16 g_w1l [(size_t)QKV_OUT * DIM];
__device__ __nv_bfloat16 g_w2h [(size_t)DIM * OUT_DIM];
__device__ __nv_bfloat16 g_w2l [(size_t)DIM * OUT_DIM];
__device__ __nv_bfloat16 g_qh  [(size_t)BATCH * NHEAD * SEQ * KDIM];
__device__ __nv_bfloat16 g_ql  [(size_t)BATCH * NHEAD * SEQ * KDIM];
__device__ __nv_bfloat16 g_kh  [(size_t)BATCH * NHEAD * SEQ * KDIM];
__device__ __nv_bfloat16 g_kl  [(size_t)BATCH * NHEAD * SEQ * KDIM];
__device__ __nv_bfloat16 g_vth [(size_t)BATCH * NHEAD * VDIM * SEQ];
__device__ __nv_bfloat16 g_vtl [(size_t)BATCH * NHEAD * VDIM * SEQ];
__device__ __nv_bfloat16 g_aoh [(size_t)MROWS * OUT_DIM];
__device__ __nv_bfloat16 g_aol [(size_t)MROWS * OUT_DIM];

// ---------------- helpers ----------------
__device__ __forceinline__ uint32_t pack_bf2(float lo, float hi) {
    uint32_t d;
    asm("cvt.rn.bf16x2.f32 %0, %1, %2;" : "=r"(d) : "f"(hi), "f"(lo));
    return d;
}
__device__ __forceinline__ void split2(float x, float y, uint32_t& hi, uint32_t& lo) {
    hi = pack_bf2(x, y);
    __nv_bfloat162 h = *reinterpret_cast<__nv_bfloat162*>(&hi);
    lo = pack_bf2(x - __bfloat162float(h.x), y - __bfloat162float(h.y));
}
__device__ __forceinline__ void mma16816(float* c, const uint32_t* a, const uint32_t* b) {
    asm volatile(
        "mma.sync.aligned.m16n8k16.row.col.f32.bf16.bf16.f32 "
        "{%0,%1,%2,%3}, {%4,%5,%6,%7}, {%8,%9}, {%0,%1,%2,%3};"
        : "+f"(c[0]), "+f"(c[1]), "+f"(c[2]), "+f"(c[3])
        : "r"(a[0]), "r"(a[1]), "r"(a[2]), "r"(a[3]), "r"(b[0]), "r"(b[1]));
}
__device__ __forceinline__ void ldm_x4(uint32_t* r, uint32_t addr) {
    asm volatile("ldmatrix.sync.aligned.m8n8.x4.shared.b16 {%0,%1,%2,%3}, [%4];"
        : "=r"(r[0]), "=r"(r[1]), "=r"(r[2]), "=r"(r[3]) : "r"(addr));
}
__device__ __forceinline__ uint32_t smem_u32(const void* p) {
    uint32_t a;
    asm("{ .reg .u64 t; cvta.to.shared.u64 t, %1; cvt.u32.u64 %0, t; }" : "=r"(a) : "l"(p));
    return a;
}
__device__ __forceinline__ void cpa16(uint32_t dst, const void* src) {
    asm volatile("cp.async.cg.shared.global [%0], [%1], 16;" :: "r"(dst), "l"(src));
}
#define CP_COMMIT() asm volatile("cp.async.commit_group;" ::: "memory")
#define CP_WAIT1()  asm volatile("cp.async.wait_group 1;" ::: "memory")

// ============================================================
// LayerNorm -> split bf16
// ============================================================
__global__ void ln_kernel(const float* __restrict__ x,
                          const float* __restrict__ gamma,
                          const float* __restrict__ beta) {
    int row = blockIdx.x;
    int t = threadIdx.x;  // 128
    const float4* xr = reinterpret_cast<const float4*>(x + (size_t)row * DIM);
    float4 v = xr[t];
    float s = v.x + v.y + v.z + v.w;
    __shared__ float red1[4];
    __shared__ float red2[4];
    #pragma unroll
    for (int o = 16; o > 0; o >>= 1) s += __shfl_xor_sync(0xffffffffu, s, o);
    if ((t & 31) == 0) red1[t >> 5] = s;
    __syncthreads();
    float mean = (red1[0] + red1[1] + red1[2] + red1[3]) * (1.0f / DIM);
    float4 d = make_float4(v.x - mean, v.y - mean, v.z - mean, v.w - mean);
    float vs = d.x*d.x + d.y*d.y + d.z*d.z + d.w*d.w;
    #pragma unroll
    for (int o = 16; o > 0; o >>= 1) vs += __shfl_xor_sync(0xffffffffu, vs, o);
    if ((t & 31) == 0) red2[t >> 5] = vs;
    __syncthreads();
    float var = (red2[0] + red2[1] + red2[2] + red2[3]) * (1.0f / DIM);
    float rs = rsqrtf(var + 1e-5f);
    float4 g  = reinterpret_cast<const float4*>(gamma)[t];
    float4 bb = reinterpret_cast<const float4*>(beta)[t];
    float o0 = d.x * rs * g.x + bb.x;
    float o1 = d.y * rs * g.y + bb.y;
    float o2 = d.z * rs * g.z + bb.z;
    float o3 = d.w * rs * g.w + bb.w;
    uint32_t h0, l0, h1, l1;
    split2(o0, o1, h0, l0); split2(o2, o3, h1, l1);
    size_t base = (size_t)row * DIM + t * 4;
    *(uint2*)(g_xh + base) = make_uint2(h0, h1);
    *(uint2*)(g_xl + base) = make_uint2(l0, l1);
}

// ============================================================
// Weight split
// ============================================================
__global__ void split_w_kernel(const float* __restrict__ w,
                               __nv_bfloat16* __restrict__ hi,
                               __nv_bfloat16* __restrict__ lo) {
    int i = blockIdx.x * 256 + threadIdx.x;
    float4 v = reinterpret_cast<const float4*>(w)[i];
    uint32_t h0, l0, h1, l1;
    split2(v.x, v.y, h0, l0); split2(v.z, v.w, h1, l1);
    size_t base = (size_t)i * 4;
    *(uint2*)(hi + base) = make_uint2(h0, h1);
    *(uint2*)(lo + base) = make_uint2(l0, l1);
}

// ============================================================
// bias pre-gather
// ============================================================
__global__ void bias_pre_kernel(const float* __restrict__ ab,
                                const int* __restrict__ bidx) {
    __shared__ float tbl[SEQ];
    int q = blockIdx.x, h = blockIdx.y, t = threadIdx.x;
    #pragma unroll
    for (int i = 0; i < 4; i++) tbl[t + 256 * i] = ab[h * SEQ + t + 256 * i];
    __syncthreads();
    int4 idx = *(const int4*)(bidx + (size_t)q * SEQ + 4 * t);
    float4 o = make_float4(tbl[idx.x], tbl[idx.y], tbl[idx.z], tbl[idx.w]);
    *(float4*)(g_bias + ((size_t)h * SEQ + q) * SEQ + 4 * t) = o;
}

// ============================================================
// qkv split/transpose
// ============================================================
__global__ void qkv_split_kernel(const float* __restrict__ qkv) {
    __shared__ __nv_bfloat16 sVH[128 * 72];
    __shared__ __nv_bfloat16 sVL[128 * 72];
    int t = threadIdx.x;
    int n0 = blockIdx.x * 64, h = blockIdx.y, b = blockIdx.z;
    size_t bh = (size_t)b * NHEAD + h;

    #pragma unroll
    for (int j = 0; j < 8; j++) {
        int id = t + 256 * j;
        int r = id >> 5, c = (id & 31) * 2;
        float2 v = *(const float2*)(qkv + ((size_t)((b * SEQ + n0 + r) * NHEAD + h)) * QKVD + c);
        uint32_t hi, lo;
        if (c < 32) {
            split2(v.x * ATT_SCALE, v.y * ATT_SCALE, hi, lo);
            size_t o = (bh * SEQ + n0 + r) * KDIM + c;
            *(uint32_t*)(g_qh + o) = hi;
            *(uint32_t*)(g_ql + o) = lo;
        } else {
            split2(v.x, v.y, hi, lo);
            size_t o = (bh * SEQ + n0 + r) * KDIM + (c - 32);
            *(uint32_t*)(g_kh + o) = hi;
            *(uint32_t*)(g_kl + o) = lo;
        }
    }
    #pragma unroll
    for (int j = 0; j < 16; j++) {
        int id = t + 256 * j;
        int r = id >> 6, c = (id & 63) * 2;
        float2 v = *(const float2*)(qkv + ((size_t)((b * SEQ + n0 + r) * NHEAD + h)) * QKVD + 2 * KDIM + c);
        __nv_bfloat16 hx = __float2bfloat16(v.x);
        __nv_bfloat16 hy = __float2bfloat16(v.y);
        sVH[c * 72 + r]       = hx;
        sVH[(c + 1) * 72 + r] = hy;
        sVL[c * 72 + r]       = __float2bfloat16(v.x - __bfloat162float(hx));
        sVL[(c + 1) * 72 + r] = __float2bfloat16(v.y - __bfloat162float(hy));
    }
    __syncthreads();
    #pragma unroll
    for (int j = 0; j < 4; j++) {
        int id = t + 256 * j;
        int r = id >> 3, cj = (id & 7) * 8;
        size_t o = (bh * VDIM + r) * SEQ + n0 + cj;
        *(uint4*)(g_vth + o) = *(const uint4*)(sVH + r * 72 + cj);
        *(uint4*)(g_vtl + o) = *(const uint4*)(sVL + r * 72 + cj);
    }
}

// ============================================================
// HMMA GEMM (split bf16 in, fp32 out), 128x128, BK=32, cp.async x2,
// ldmatrix operand loads.
// ============================================================
__device__ __forceinline__ void gemm_issue_stage(
    uint32_t sb_u32, int stage, int kc,
    const __nv_bfloat16* Ah, const __nv_bfloat16* Al,
    const __nv_bfloat16* Bh, const __nv_bfloat16* Bl,
    int m0, int n0, int K, int t)
{
    uint32_t base = sb_u32 + stage * 20480 * 2;
    #pragma unroll
    for (int j = 0; j < 2; j++) {
        int id = t + 256 * j;
        int r = id >> 2, c = (id & 3) * 8;
        uint32_t so = (r * 40 + c) * 2;
        size_t ga = (size_t)(m0 + r) * K + kc * 32 + c;
        size_t gb = (size_t)(n0 + r) * K + kc * 32 + c;
        cpa16(base + so,             Ah + ga);
        cpa16(base + 5120 * 2 + so,  Al + ga);
        cpa16(base + 10240 * 2 + so, Bh + gb);
        cpa16(base + 15360 * 2 + so, Bl + gb);
    }
}

__global__ __launch_bounds__(256)
void gemm_bf_kernel(const __nv_bfloat16* __restrict__ Ah, const __nv_bfloat16* __restrict__ Al,
                    const __nv_bfloat16* __restrict__ Bh, const __nv_bfloat16* __restrict__ Bl,
                    const float* __restrict__ bias, float* __restrict__ C,
                    int M, int N, int K)
{
    extern __shared__ __align__(16) char smc[];
    uint32_t sb_u32 = smem_u32(smc);

    const int t = threadIdx.x;
    const int m0 = blockIdx.x * 128, n0 = blockIdx.y * 128;
    const int lane = t & 31, warp = t >> 5;
    const int g = lane >> 2, tid4 = lane & 3;
    const int wm = warp >> 2, wn = warp & 3;

    const int ar_part = (lane & 7) + 8 * ((lane >> 3) & 1);
    const int ac_part = 8 * (lane >> 4);
    const int br_part = 8 * (lane >> 4) + (lane & 7);
    const int bc_part = 8 * ((lane >> 3) & 1);

    float acc[4][4][4];
    #pragma unroll
    for (int a = 0; a < 4; a++)
        #pragma unroll
        for (int bq = 0; bq < 4; bq++)
            #pragma unroll
            for (int e = 0; e < 4; e++) acc[a][bq][e] = 0.f;

    int nk = K >> 5;
    gemm_issue_stage(sb_u32, 0, 0, Ah, Al, Bh, Bl, m0, n0, K, t);
    CP_COMMIT();
    gemm_issue_stage(sb_u32, 1, 1, Ah, Al, Bh, Bl, m0, n0, K, t);
    CP_COMMIT();

    for (int kc = 0; kc < nk; kc++) {
        CP_WAIT1();
        __syncthreads();
        uint32_t st = sb_u32 + (kc & 1) * 40960;
        #pragma unroll
        for (int kt2 = 0; kt2 < 2; kt2++) {
            uint32_t ah[4][4], al[4][4];
            #pragma unroll
            for (int mt = 0; mt < 4; mt++) {
                uint32_t aaddr = st + ((64 * wm + 16 * mt + ar_part) * 40 + 16 * kt2 + ac_part) * 2;
                ldm_x4(ah[mt], aaddr);
                ldm_x4(al[mt], aaddr + 10240);
            }
            #pragma unroll
            for (int jj = 0; jj < 2; jj++) {
                uint32_t baddr = st + 20480 +
                    ((32 * wn + 16 * jj + br_part) * 40 + 16 * kt2 + bc_part) * 2;
                uint32_t bh[4], bl[4];
                ldm_x4(bh, baddr);
                ldm_x4(bl, baddr + 10240);
                #pragma unroll
                for (int mt = 0; mt < 4; mt++) {
                    mma16816(acc[mt][2*jj],   ah[mt], bh);
                    mma16816(acc[mt][2*jj],   ah[mt], bl);
                    mma16816(acc[mt][2*jj],   al[mt], bh);
                    mma16816(acc[mt][2*jj+1], ah[mt], bh + 2);
                    mma16816(acc[mt][2*jj+1], ah[mt], bl + 2);
                    mma16816(acc[mt][2*jj+1], al[mt], bh + 2);
                }
            }
        }
        __syncthreads();
        if (kc + 2 < nk)
            gemm_issue_stage(sb_u32, kc & 1, kc + 2, Ah, Al, Bh, Bl, m0, n0, K, t);
        CP_COMMIT();
    }

    #pragma unroll
    for (int mt = 0; mt < 4; mt++) {
        int row = m0 + 64 * wm + 16 * mt + g;
        #pragma unroll
        for (int nt = 0; nt < 4; nt++) {
            int col = n0 + 32 * wn + 8 * nt + 2 * tid4;
            float2 bv = *(const float2*)(bias + col);
            float2 v0 = make_float2(acc[mt][nt][0] + bv.x, acc[mt][nt][1] + bv.y);
            float2 v1 = make_float2(acc[mt][nt][2] + bv.x, acc[mt][nt][3] + bv.y);
            *(float2*)(C + (size_t)row * N + col)       = v0;
            *(float2*)(C + (size_t)(row + 8) * N + col) = v1;
        }
    }
}

// ============================================================
// HMMA flash attention: 128 queries/block, 256 threads (8 warps),
// ldmatrix operands, no-max softmax, cp.async double-buffered.
// smem elems: QH 0 | QL 5120 | stage s at 10240+s*23552:
//   KH +0 | KL +2560 | VH +5120 (128x72) | VL +14336
// ============================================================
#define A_OQL 5120
#define A_OST 10240
#define A_STS 23552
#define A_OVH 5120

__device__ __forceinline__ void attn_issue_stage(
    uint32_t sb_u32, int stage, int k0, size_t bh, int t)
{
    uint32_t base = sb_u32 + (A_OST + stage * A_STS) * 2;
    {   // K: 64 rows x 32 cols, hi+lo
        int r = t >> 2, c = (t & 3) * 8;
        uint32_t so = (r * 40 + c) * 2;
        size_t gk = (bh * SEQ + k0 + r) * KDIM + c;
        cpa16(base + so,        g_kh + gk);
        cpa16(base + 5120 + so, g_kl + gk);
    }
    #pragma unroll
    for (int j = 0; j < 4; j++) {   // V: 128 rows x 64 cols, hi+lo
        int id = t + 256 * j;
        int r = id >> 3, c = (id & 7) * 8;
        uint32_t so = (r * 72 + c) * 2;
        size_t gv = (bh * VDIM + r) * SEQ + k0 + c;
        cpa16(base + 10240 + so, g_vth + gv);
        cpa16(base + 28672 + so, g_vtl + gv);
    }
}

__global__ __launch_bounds__(256, 1)
void attn_mma_kernel() {
    extern __shared__ __align__(16) char smc[];
    uint32_t sb_u32 = smem_u32(smc);

    const int t = threadIdx.x, lane = t & 31, warp = t >> 5;
    const int g = lane >> 2, tid4 = lane & 3;
    const int qb = blockIdx.x, b = blockIdx.y, h = blockIdx.z;
    const int q0 = qb * 128;
    const size_t bh = (size_t)b * NHEAD + h;

    const int qr_part = 16 * warp + (lane & 7) + 8 * ((lane >> 3) & 1);
    const int qc_part = 8 * (lane >> 4);
    const int kr_part = 8 * (lane >> 4) + (lane & 7);
    const int kc_part = 8 * ((lane >> 3) & 1);
    const int vr_part = lane & 7;
    const int vc_part = 8 * (lane >> 3);

    // stage Q (128 rows x 32 cols hi+lo) + first two K/V tiles
    #pragma unroll
    for (int j = 0; j < 2; j++) {
        int id = t + 256 * j;
        int r = id >> 2, c = (id & 3) * 8;
        uint32_t so = (r * 40 + c) * 2;
        size_t gq = (bh * SEQ + q0 + r) * KDIM + c;
        cpa16(sb_u32 + so,           g_qh + gq);
        cpa16(sb_u32 + 10240 + so,   g_ql + gq);
    }
    attn_issue_stage(sb_u32, 0, 0, bh, t);
    CP_COMMIT();
    attn_issue_stage(sb_u32, 1, 64, bh, t);
    CP_COMMIT();

    CP_WAIT1();
    __syncthreads();
    uint32_t qa_h[2][4], qa_l[2][4];
    {
        uint32_t qaddr = sb_u32 + (qr_part * 40 + qc_part) * 2;
        ldm_x4(qa_h[0], qaddr);
        ldm_x4(qa_h[1], qaddr + 32);
        ldm_x4(qa_l[0], qaddr + 10240);
        ldm_x4(qa_l[1], qaddr + 10240 + 32);
    }

    float o[16][4];
    #pragma unroll
    for (int nt = 0; nt < 16; nt++)
        #pragma unroll
        for (int e = 0; e < 4; e++) o[nt][e] = 0.f;
    float lsum0 = 0.f, lsum1 = 0.f;
    const int r0 = q0 + 16 * warp + g;
    const int r1 = r0 + 8;

    for (int it = 0; it < 16; it++) {
        CP_WAIT1();
        __syncthreads();
        const int k0 = it * 64;
        uint32_t sK = sb_u32 + (A_OST + (it & 1) * A_STS) * 2;
        uint32_t sV = sK + A_OVH * 2;

        // ---- QK ----
        float s[8][4];
        #pragma unroll
        for (int j = 0; j < 8; j++)
            #pragma unroll
            for (int e = 0; e < 4; e++) s[j][e] = 0.f;
        #pragma unroll
        for (int kt2 = 0; kt2 < 2; kt2++) {
            #pragma unroll
            for (int jj = 0; jj < 4; jj++) {
                uint32_t kaddr = sK + ((16 * jj + kr_part) * 40 + 16 * kt2 + kc_part) * 2;
                uint32_t kh[4], kl[4];
                ldm_x4(kh, kaddr);
                ldm_x4(kl, kaddr + 5120);
                mma16816(s[2*jj],   qa_h[kt2], kh);
                mma16816(s[2*jj],   qa_h[kt2], kl);
                mma16816(s[2*jj],   qa_l[kt2], kh);
                mma16816(s[2*jj+1], qa_h[kt2], kh + 2);
                mma16816(s[2*jj+1], qa_h[kt2], kl + 2);
                mma16816(s[2*jj+1], qa_l[kt2], kh + 2);
            }
        }

        // ---- bias + exp (no max-shift; scores bounded) ----
        const float* bbase0 = g_bias + ((size_t)h * SEQ + r0) * SEQ + k0 + 2 * tid4;
        const float* bbase1 = g_bias + ((size_t)h * SEQ + r1) * SEQ + k0 + 2 * tid4;
        uint32_t pa_h[4][4], pa_l[4][4];
        #pragma unroll
        for (int j = 0; j < 8; j++) {
            float2 b0v = *(const float2*)(bbase0 + 8 * j);
            float2 b1v = *(const float2*)(bbase1 + 8 * j);
            s[j][0] = __expf(s[j][0] + b0v.x);
            s[j][1] = __expf(s[j][1] + b0v.y);
            s[j][2] = __expf(s[j][2] + b1v.x);
            s[j][3] = __expf(s[j][3] + b1v.y);
            lsum0 += s[j][0] + s[j][1];
            lsum1 += s[j][2] + s[j][3];
        }
        #pragma unroll
        for (int u = 0; u < 4; u++) {
            split2(s[2*u][0],   s[2*u][1],   pa_h[u][0], pa_l[u][0]);
            split2(s[2*u][2],   s[2*u][3],   pa_h[u][1], pa_l[u][1]);
            split2(s[2*u+1][0], s[2*u+1][1], pa_h[u][2], pa_l[u][2]);
            split2(s[2*u+1][2], s[2*u+1][3], pa_h[u][3], pa_l[u][3]);
        }

        // ---- PV ----
        #pragma unroll
        for (int nt = 0; nt < 16; nt++) {
            uint32_t vaddr = sV + ((8 * nt + vr_part) * 72 + vc_part) * 2;
            uint32_t vh[8], vl[8];
            ldm_x4(vh,     vaddr);
            ldm_x4(vh + 4, vaddr + 64);
            ldm_x4(vl,     vaddr + 18432);
            ldm_x4(vl + 4, vaddr + 18432 + 64);
            #pragma unroll
            for (int u = 0; u < 4; u++) {
                mma16816(o[nt], pa_h[u], vh + 2 * u);
                mma16816(o[nt], pa_h[u], vl + 2 * u);
                mma16816(o[nt], pa_l[u], vh + 2 * u);
            }
        }
        __syncthreads();
        if (it + 2 < 16)
            attn_issue_stage(sb_u32, it & 1, (it + 2) * 64, bh, t);
        CP_COMMIT();
    }

    lsum0 += __shfl_xor_sync(0xffffffffu, lsum0, 1);
    lsum0 += __shfl_xor_sync(0xffffffffu, lsum0, 2);
    lsum1 += __shfl_xor_sync(0xffffffffu, lsum1, 1);
    lsum1 += __shfl_xor_sync(0xffffffffu, lsum1, 2);
    float i0 = 1.f / lsum0, i1 = 1.f / lsum1;
    #pragma unroll
    for (int nt = 0; nt < 16; nt++) {
        int col = h * VDIM + 8 * nt + 2 * tid4;
        uint32_t hh, ll;
        split2(o[nt][0] * i0, o[nt][1] * i0, hh, ll);
        size_t o0 = (size_t)(b * SEQ + r0) * OUT_DIM + col;
        *(uint32_t*)(g_aoh + o0) = hh;
        *(uint32_t*)(g_aol + o0) = ll;
        split2(o[nt][2] * i1, o[nt][3] * i1, hh, ll);
        size_t o1 = (size_t)(b * SEQ + r1) * OUT_DIM + col;
        *(uint32_t*)(g_aoh + o1) = hh;
        *(uint32_t*)(g_aol + o1) = ll;
    }
}

// ============================================================
// launch
// ============================================================
extern "C" void kernel_launch(void* const* d_in, const int* in_sizes, int n_in,
                              void* d_out, int out_size) {
    const float* x     = (const float*)d_in[0];
    const float* gamma = (const float*)d_in[1];
    const float* beta  = (const float*)d_in[2];
    const float* Wqkv  = (const float*)d_in[3];
    const float* bqkv  = (const float*)d_in[4];
    const float* Wproj = (const float*)d_in[5];
    const float* bproj = (const float*)d_in[6];
    const float* ab    = (const float*)d_in[7];
    const int*   bidx  = (const int*)d_in[8];
    float* out = (float*)d_out;

    void *pqkv, *pxh, *pxl, *pw1h, *pw1l, *pw2h, *pw2l, *paoh, *paol;
    cudaGetSymbolAddress(&pqkv, g_qkv);
    cudaGetSymbolAddress(&pxh, g_xh);   cudaGetSymbolAddress(&pxl, g_xl);
    cudaGetSymbolAddress(&pw1h, g_w1h); cudaGetSymbolAddress(&pw1l, g_w1l);
    cudaGetSymbolAddress(&pw2h, g_w2h); cudaGetSymbolAddress(&pw2l, g_w2l);
    cudaGetSymbolAddress(&paoh, g_aoh); cudaGetSymbolAddress(&paol, g_aol);

    const int gemm_smem = 40960 * 2;
    const int attn_smem = (A_OST + 2 * A_STS) * 2;   // 114688 B
    cudaFuncSetAttribute(gemm_bf_kernel,
                         cudaFuncAttributeMaxDynamicSharedMemorySize, gemm_smem);
    cudaFuncSetAttribute(attn_mma_kernel,
                         cudaFuncAttributeMaxDynamicSharedMemorySize, attn_smem);

    ln_kernel<<<MROWS, 128>>>(x, gamma, beta);
    split_w_kernel<<<(QKV_OUT * DIM / 4) / 256, 256>>>(
        Wqkv, (__nv_bfloat16*)pw1h, (__nv_bfloat16*)pw1l);
    split_w_kernel<<<(DIM * OUT_DIM / 4) / 256, 256>>>(
        Wproj, (__nv_bfloat16*)pw2h, (__nv_bfloat16*)pw2l);
    bias_pre_kernel<<<dim3(SEQ, NHEAD), 256>>>(ab, bidx);

    gemm_bf_kernel<<<dim3(MROWS / 128, QKV_OUT / 128), 256, gemm_smem>>>(
        (const __nv_bfloat16*)pxh, (const __nv_bfloat16*)pxl,
        (const __nv_bfloat16*)pw1h, (const __nv_bfloat16*)pw1l,
        bqkv, (float*)pqkv, MROWS, QKV_OUT, DIM);

    qkv_split_kernel<<<dim3(SEQ / 64, NHEAD, BATCH), 256>>>((const float*)pqkv);

    attn_mma_kernel<<<dim3(SEQ / 128, BATCH, NHEAD), 256, attn_smem>>>();

    gemm_bf_kernel<<<dim3(MROWS / 128, DIM / 128), 256, gemm_smem>>>(
        (const __nv_bfloat16*)paoh, (const __nv_bfloat16*)paol,
        (const __nv_bfloat16*)pw2h, (const __nv_bfloat16*)pw2l,
        bproj, out, MROWS, DIM, OUT_DIM);
}

// round 8
// speedup vs baseline: 1.0043x; 1.0043x over previous
#include <cuda_runtime.h>
#include <cuda_bf16.h>
#include <math.h>
#include <stdint.h>

#define BATCH   16
#define SEQ     1024
#define DIM     512
#define NHEAD   16
#define KDIM    32
#define VDIM    128
#define QKVD    192
#define QKV_OUT 3072
#define OUT_DIM 2048
#define MROWS   16384
#define ATT_SCALE 0.17677669529663687f
#define LOG2E     1.4426950408889634f

// ---------------- scratch ----------------
__device__ float         g_qkv [(size_t)MROWS * QKV_OUT];
__device__ float         g_bias[(size_t)NHEAD * SEQ * SEQ];
__device__ __nv_bfloat16 g_xh  [(size_t)MROWS * DIM];
__device__ __nv_bfloat16 g_xl  [(size_t)MROWS * DIM];
__device__ __nv_bfloat16 g_w1h [(size_t)QKV_OUT * DIM];
__device__ __nv_bfloat16 g_w1l [(size_t)QKV_OUT * DIM];
__device__ __nv_bfloat16 g_w2h [(size_t)DIM * OUT_DIM];
__device__ __nv_bfloat16 g_w2l [(size_t)DIM * OUT_DIM];
__device__ __nv_bfloat16 g_qh  [(size_t)BATCH * NHEAD * SEQ * KDIM];
__device__ __nv_bfloat16 g_ql  [(size_t)BATCH * NHEAD * SEQ * KDIM];
__device__ __nv_bfloat16 g_kh  [(size_t)BATCH * NHEAD * SEQ * KDIM];
__device__ __nv_bfloat16 g_kl  [(size_t)BATCH * NHEAD * SEQ * KDIM];
__device__ __nv_bfloat16 g_vth [(size_t)BATCH * NHEAD * VDIM * SEQ];
__device__ __nv_bfloat16 g_vtl [(size_t)BATCH * NHEAD * VDIM * SEQ];
__device__ __nv_bfloat16 g_aoh [(size_t)MROWS * OUT_DIM];
__device__ __nv_bfloat16 g_aol [(size_t)MROWS * OUT_DIM];

// ---------------- helpers ----------------
__device__ __forceinline__ uint32_t pack_bf2(float lo, float hi) {
    uint32_t d;
    asm("cvt.rn.bf16x2.f32 %0, %1, %2;" : "=r"(d) : "f"(hi), "f"(lo));
    return d;
}
__device__ __forceinline__ void split2(float x, float y, uint32_t& hi, uint32_t& lo) {
    hi = pack_bf2(x, y);
    __nv_bfloat162 h = *reinterpret_cast<__nv_bfloat162*>(&hi);
    lo = pack_bf2(x - __bfloat162float(h.x), y - __bfloat162float(h.y));
}
__device__ __forceinline__ float ex2(float x) {
    float r;
    asm("ex2.approx.f32 %0, %1;" : "=f"(r) : "f"(x));
    return r;
}
__device__ __forceinline__ void mma16816(float* c, const uint32_t* a, const uint32_t* b) {
    asm volatile(
        "mma.sync.aligned.m16n8k16.row.col.f32.bf16.bf16.f32 "
        "{%0,%1,%2,%3}, {%4,%5,%6,%7}, {%8,%9}, {%0,%1,%2,%3};"
        : "+f"(c[0]), "+f"(c[1]), "+f"(c[2]), "+f"(c[3])
        : "r"(a[0]), "r"(a[1]), "r"(a[2]), "r"(a[3]), "r"(b[0]), "r"(b[1]));
}
__device__ __forceinline__ void ldm_x4(uint32_t* r, uint32_t addr) {
    asm volatile("ldmatrix.sync.aligned.m8n8.x4.shared.b16 {%0,%1,%2,%3}, [%4];"
        : "=r"(r[0]), "=r"(r[1]), "=r"(r[2]), "=r"(r[3]) : "r"(addr));
}
__device__ __forceinline__ uint32_t smem_u32(const void* p) {
    uint32_t a;
    asm("{ .reg .u64 t; cvta.to.shared.u64 t, %1; cvt.u32.u64 %0, t; }" : "=r"(a) : "l"(p));
    return a;
}
__device__ __forceinline__ void cpa16(uint32_t dst, const void* src) {
    asm volatile("cp.async.cg.shared.global [%0], [%1], 16;" :: "r"(dst), "l"(src));
}
#define CP_COMMIT() asm volatile("cp.async.commit_group;" ::: "memory")
#define CP_WAIT1()  asm volatile("cp.async.wait_group 1;" ::: "memory")

// ============================================================
// LayerNorm -> split bf16
// ============================================================
__global__ void ln_kernel(const float* __restrict__ x,
                          const float* __restrict__ gamma,
                          const float* __restrict__ beta) {
    int row = blockIdx.x;
    int t = threadIdx.x;  // 128
    const float4* xr = reinterpret_cast<const float4*>(x + (size_t)row * DIM);
    float4 v = xr[t];
    float s = v.x + v.y + v.z + v.w;
    __shared__ float red1[4];
    __shared__ float red2[4];
    #pragma unroll
    for (int o = 16; o > 0; o >>= 1) s += __shfl_xor_sync(0xffffffffu, s, o);
    if ((t & 31) == 0) red1[t >> 5] = s;
    __syncthreads();
    float mean = (red1[0] + red1[1] + red1[2] + red1[3]) * (1.0f / DIM);
    float4 d = make_float4(v.x - mean, v.y - mean, v.z - mean, v.w - mean);
    float vs = d.x*d.x + d.y*d.y + d.z*d.z + d.w*d.w;
    #pragma unroll
    for (int o = 16; o > 0; o >>= 1) vs += __shfl_xor_sync(0xffffffffu, vs, o);
    if ((t & 31) == 0) red2[t >> 5] = vs;
    __syncthreads();
    float var = (red2[0] + red2[1] + red2[2] + red2[3]) * (1.0f / DIM);
    float rs = rsqrtf(var + 1e-5f);
    float4 g  = reinterpret_cast<const float4*>(gamma)[t];
    float4 bb = reinterpret_cast<const float4*>(beta)[t];
    float o0 = d.x * rs * g.x + bb.x;
    float o1 = d.y * rs * g.y + bb.y;
    float o2 = d.z * rs * g.z + bb.z;
    float o3 = d.w * rs * g.w + bb.w;
    uint32_t h0, l0, h1, l1;
    split2(o0, o1, h0, l0); split2(o2, o3, h1, l1);
    size_t base = (size_t)row * DIM + t * 4;
    *(uint2*)(g_xh + base) = make_uint2(h0, h1);
    *(uint2*)(g_xl + base) = make_uint2(l0, l1);
}

// ============================================================
// Weight split
// ============================================================
__global__ void split_w_kernel(const float* __restrict__ w,
                               __nv_bfloat16* __restrict__ hi,
                               __nv_bfloat16* __restrict__ lo) {
    int i = blockIdx.x * 256 + threadIdx.x;
    float4 v = reinterpret_cast<const float4*>(w)[i];
    uint32_t h0, l0, h1, l1;
    split2(v.x, v.y, h0, l0); split2(v.z, v.w, h1, l1);
    size_t base = (size_t)i * 4;
    *(uint2*)(hi + base) = make_uint2(h0, h1);
    *(uint2*)(lo + base) = make_uint2(l0, l1);
}

// ============================================================
// bias pre-gather (pre-multiplied by log2e for ex2 softmax)
// ============================================================
__global__ void bias_pre_kernel(const float* __restrict__ ab,
                                const int* __restrict__ bidx) {
    __shared__ float tbl[SEQ];
    int q = blockIdx.x, h = blockIdx.y, t = threadIdx.x;
    #pragma unroll
    for (int i = 0; i < 4; i++) tbl[t + 256 * i] = ab[h * SEQ + t + 256 * i] * LOG2E;
    __syncthreads();
    int4 idx = *(const int4*)(bidx + (size_t)q * SEQ + 4 * t);
    float4 o = make_float4(tbl[idx.x], tbl[idx.y], tbl[idx.z], tbl[idx.w]);
    *(float4*)(g_bias + ((size_t)h * SEQ + q) * SEQ + 4 * t) = o;
}

// ============================================================
// qkv split/transpose (q scaled by ATT_SCALE*log2e)
// ============================================================
__global__ void qkv_split_kernel(const float* __restrict__ qkv) {
    __shared__ __nv_bfloat16 sVH[128 * 72];
    __shared__ __nv_bfloat16 sVL[128 * 72];
    int t = threadIdx.x;
    int n0 = blockIdx.x * 64, h = blockIdx.y, b = blockIdx.z;
    size_t bh = (size_t)b * NHEAD + h;
    const float QSC = ATT_SCALE * LOG2E;

    #pragma unroll
    for (int j = 0; j < 8; j++) {
        int id = t + 256 * j;
        int r = id >> 5, c = (id & 31) * 2;
        float2 v = *(const float2*)(qkv + ((size_t)((b * SEQ + n0 + r) * NHEAD + h)) * QKVD + c);
        uint32_t hi, lo;
        if (c < 32) {
            split2(v.x * QSC, v.y * QSC, hi, lo);
            size_t o = (bh * SEQ + n0 + r) * KDIM + c;
            *(uint32_t*)(g_qh + o) = hi;
            *(uint32_t*)(g_ql + o) = lo;
        } else {
            split2(v.x, v.y, hi, lo);
            size_t o = (bh * SEQ + n0 + r) * KDIM + (c - 32);
            *(uint32_t*)(g_kh + o) = hi;
            *(uint32_t*)(g_kl + o) = lo;
        }
    }
    #pragma unroll
    for (int j = 0; j < 16; j++) {
        int id = t + 256 * j;
        int r = id >> 6, c = (id & 63) * 2;
        float2 v = *(const float2*)(qkv + ((size_t)((b * SEQ + n0 + r) * NHEAD + h)) * QKVD + 2 * KDIM + c);
        __nv_bfloat16 hx = __float2bfloat16(v.x);
        __nv_bfloat16 hy = __float2bfloat16(v.y);
        sVH[c * 72 + r]       = hx;
        sVH[(c + 1) * 72 + r] = hy;
        sVL[c * 72 + r]       = __float2bfloat16(v.x - __bfloat162float(hx));
        sVL[(c + 1) * 72 + r] = __float2bfloat16(v.y - __bfloat162float(hy));
    }
    __syncthreads();
    #pragma unroll
    for (int j = 0; j < 4; j++) {
        int id = t + 256 * j;
        int r = id >> 3, cj = (id & 7) * 8;
        size_t o = (bh * VDIM + r) * SEQ + n0 + cj;
        *(uint4*)(g_vth + o) = *(const uint4*)(sVH + r * 72 + cj);
        *(uint4*)(g_vtl + o) = *(const uint4*)(sVL + r * 72 + cj);
    }
}

// ============================================================
// HMMA GEMM (split bf16 in, fp32 out), 128x128, BK=32, cp.async x2,
// ldmatrix operand loads.
// ============================================================
__device__ __forceinline__ void gemm_issue_stage(
    uint32_t sb_u32, int stage, int kc,
    const __nv_bfloat16* Ah, const __nv_bfloat16* Al,
    const __nv_bfloat16* Bh, const __nv_bfloat16* Bl,
    int m0, int n0, int K, int t)
{
    uint32_t base = sb_u32 + stage * 20480 * 2;
    #pragma unroll
    for (int j = 0; j < 2; j++) {
        int id = t + 256 * j;
        int r = id >> 2, c = (id & 3) * 8;
        uint32_t so = (r * 40 + c) * 2;
        size_t ga = (size_t)(m0 + r) * K + kc * 32 + c;
        size_t gb = (size_t)(n0 + r) * K + kc * 32 + c;
        cpa16(base + so,             Ah + ga);
        cpa16(base + 5120 * 2 + so,  Al + ga);
        cpa16(base + 10240 * 2 + so, Bh + gb);
        cpa16(base + 15360 * 2 + so, Bl + gb);
    }
}

__global__ __launch_bounds__(256)
void gemm_bf_kernel(const __nv_bfloat16* __restrict__ Ah, const __nv_bfloat16* __restrict__ Al,
                    const __nv_bfloat16* __restrict__ Bh, const __nv_bfloat16* __restrict__ Bl,
                    const float* __restrict__ bias, float* __restrict__ C,
                    int M, int N, int K)
{
    extern __shared__ __align__(16) char smc[];
    uint32_t sb_u32 = smem_u32(smc);

    const int t = threadIdx.x;
    const int m0 = blockIdx.x * 128, n0 = blockIdx.y * 128;
    const int lane = t & 31, warp = t >> 5;
    const int g = lane >> 2, tid4 = lane & 3;
    const int wm = warp >> 2, wn = warp & 3;

    const int ar_part = (lane & 7) + 8 * ((lane >> 3) & 1);
    const int ac_part = 8 * (lane >> 4);
    const int br_part = 8 * (lane >> 4) + (lane & 7);
    const int bc_part = 8 * ((lane >> 3) & 1);

    float acc[4][4][4];
    #pragma unroll
    for (int a = 0; a < 4; a++)
        #pragma unroll
        for (int bq = 0; bq < 4; bq++)
            #pragma unroll
            for (int e = 0; e < 4; e++) acc[a][bq][e] = 0.f;

    int nk = K >> 5;
    gemm_issue_stage(sb_u32, 0, 0, Ah, Al, Bh, Bl, m0, n0, K, t);
    CP_COMMIT();
    gemm_issue_stage(sb_u32, 1, 1, Ah, Al, Bh, Bl, m0, n0, K, t);
    CP_COMMIT();

    for (int kc = 0; kc < nk; kc++) {
        CP_WAIT1();
        __syncthreads();
        uint32_t st = sb_u32 + (kc & 1) * 40960;
        #pragma unroll
        for (int kt2 = 0; kt2 < 2; kt2++) {
            uint32_t ah[4][4], al[4][4];
            #pragma unroll
            for (int mt = 0; mt < 4; mt++) {
                uint32_t aaddr = st + ((64 * wm + 16 * mt + ar_part) * 40 + 16 * kt2 + ac_part) * 2;
                ldm_x4(ah[mt], aaddr);
                ldm_x4(al[mt], aaddr + 10240);
            }
            #pragma unroll
            for (int jj = 0; jj < 2; jj++) {
                uint32_t baddr = st + 20480 +
                    ((32 * wn + 16 * jj + br_part) * 40 + 16 * kt2 + bc_part) * 2;
                uint32_t bh[4], bl[4];
                ldm_x4(bh, baddr);
                ldm_x4(bl, baddr + 10240);
                #pragma unroll
                for (int mt = 0; mt < 4; mt++) {
                    mma16816(acc[mt][2*jj],   ah[mt], bh);
                    mma16816(acc[mt][2*jj],   ah[mt], bl);
                    mma16816(acc[mt][2*jj],   al[mt], bh);
                    mma16816(acc[mt][2*jj+1], ah[mt], bh + 2);
                    mma16816(acc[mt][2*jj+1], ah[mt], bl + 2);
                    mma16816(acc[mt][2*jj+1], al[mt], bh + 2);
                }
            }
        }
        __syncthreads();
        if (kc + 2 < nk)
            gemm_issue_stage(sb_u32, kc & 1, kc + 2, Ah, Al, Bh, Bl, m0, n0, K, t);
        CP_COMMIT();
    }

    #pragma unroll
    for (int mt = 0; mt < 4; mt++) {
        int row = m0 + 64 * wm + 16 * mt + g;
        #pragma unroll
        for (int nt = 0; nt < 4; nt++) {
            int col = n0 + 32 * wn + 8 * nt + 2 * tid4;
            float2 bv = *(const float2*)(bias + col);
            float2 v0 = make_float2(acc[mt][nt][0] + bv.x, acc[mt][nt][1] + bv.y);
            float2 v1 = make_float2(acc[mt][nt][2] + bv.x, acc[mt][nt][3] + bv.y);
            *(float2*)(C + (size_t)row * N + col)       = v0;
            *(float2*)(C + (size_t)(row + 8) * N + col) = v1;
        }
    }
}

// ============================================================
// HMMA flash attention: 64 q/block, 128 thr, 4 warps, 2 blocks/SM.
// ldmatrix operands, no-max ex2 softmax (log2e pre-folded),
// bias prefetched ahead of QK, cp.async double-buffered.
// smem elems: QH 0 | QL 2560 | stage s at 5120+s*23552:
//   KH +0 | KL +2560 | VH +5120 (128x72) | VL +14336
// ============================================================
#define A_OQL 2560
#define A_OST 5120
#define A_STS 23552
#define A_OVH 5120

__device__ __forceinline__ void attn_issue_stage(
    uint32_t sb_u32, int stage, int k0, size_t bh, int t)
{
    uint32_t base = sb_u32 + (A_OST + stage * A_STS) * 2;
    #pragma unroll
    for (int j = 0; j < 2; j++) {
        int id = t + 128 * j;
        int r = id >> 2, c = (id & 3) * 8;
        uint32_t so = (r * 40 + c) * 2;
        size_t gk = (bh * SEQ + k0 + r) * KDIM + c;
        cpa16(base + so,        g_kh + gk);
        cpa16(base + 5120 + so, g_kl + gk);
    }
    #pragma unroll
    for (int j = 0; j < 8; j++) {
        int id = t + 128 * j;
        int r = id >> 3, c = (id & 7) * 8;
        uint32_t so = (r * 72 + c) * 2;
        size_t gv = (bh * VDIM + r) * SEQ + k0 + c;
        cpa16(base + 10240 + so, g_vth + gv);
        cpa16(base + 28672 + so, g_vtl + gv);
    }
}

__global__ __launch_bounds__(128, 2)
void attn_mma_kernel() {
    extern __shared__ __align__(16) char smc[];
    uint32_t sb_u32 = smem_u32(smc);

    const int t = threadIdx.x, lane = t & 31, warp = t >> 5;
    const int g = lane >> 2, tid4 = lane & 3;
    const int qb = blockIdx.x, b = blockIdx.y, h = blockIdx.z;
    const int q0 = qb * 64;
    const size_t bh = (size_t)b * NHEAD + h;

    const int qr_part = 16 * warp + (lane & 7) + 8 * ((lane >> 3) & 1);
    const int qc_part = 8 * (lane >> 4);
    const int kr_part = 8 * (lane >> 4) + (lane & 7);
    const int kc_part = 8 * ((lane >> 3) & 1);
    const int vr_part = lane & 7;
    const int vc_part = 8 * (lane >> 3);

    #pragma unroll
    for (int j = 0; j < 2; j++) {
        int id = t + 128 * j;
        int r = id >> 2, c = (id & 3) * 8;
        uint32_t so = (r * 40 + c) * 2;
        size_t gq = (bh * SEQ + q0 + r) * KDIM + c;
        cpa16(sb_u32 + so,          g_qh + gq);
        cpa16(sb_u32 + 5120 + so,   g_ql + gq);
    }
    attn_issue_stage(sb_u32, 0, 0, bh, t);
    CP_COMMIT();
    attn_issue_stage(sb_u32, 1, 64, bh, t);
    CP_COMMIT();

    CP_WAIT1();
    __syncthreads();
    uint32_t qa_h[2][4], qa_l[2][4];
    {
        uint32_t qaddr = sb_u32 + (qr_part * 40 + qc_part) * 2;
        ldm_x4(qa_h[0], qaddr);
        ldm_x4(qa_h[1], qaddr + 32);
        ldm_x4(qa_l[0], qaddr + 5120);
        ldm_x4(qa_l[1], qaddr + 5120 + 32);
    }

    float o[16][4];
    #pragma unroll
    for (int nt = 0; nt < 16; nt++)
        #pragma unroll
        for (int e = 0; e < 4; e++) o[nt][e] = 0.f;
    float lsum0 = 0.f, lsum1 = 0.f;
    const int r0 = q0 + 16 * warp + g;
    const int r1 = r0 + 8;
    const float* bbase0 = g_bias + ((size_t)h * SEQ + r0) * SEQ + 2 * tid4;
    const float* bbase1 = g_bias + ((size_t)h * SEQ + r1) * SEQ + 2 * tid4;

    for (int it = 0; it < 16; it++) {
        CP_WAIT1();
        __syncthreads();
        const int k0 = it * 64;
        uint32_t sK = sb_u32 + (A_OST + (it & 1) * A_STS) * 2;
        uint32_t sV = sK + A_OVH * 2;

        // ---- prefetch bias (hides LDG behind QK MMAs) ----
        float2 b0v[8], b1v[8];
        #pragma unroll
        for (int j = 0; j < 8; j++) {
            b0v[j] = *(const float2*)(bbase0 + k0 + 8 * j);
            b1v[j] = *(const float2*)(bbase1 + k0 + 8 * j);
        }

        // ---- QK ----
        float s[8][4];
        #pragma unroll
        for (int j = 0; j < 8; j++)
            #pragma unroll
            for (int e = 0; e < 4; e++) s[j][e] = 0.f;
        #pragma unroll
        for (int kt2 = 0; kt2 < 2; kt2++) {
            #pragma unroll
            for (int jj = 0; jj < 4; jj++) {
                uint32_t kaddr = sK + ((16 * jj + kr_part) * 40 + 16 * kt2 + kc_part) * 2;
                uint32_t kh[4], kl[4];
                ldm_x4(kh, kaddr);
                ldm_x4(kl, kaddr + 5120);
                mma16816(s[2*jj],   qa_h[kt2], kh);
                mma16816(s[2*jj],   qa_h[kt2], kl);
                mma16816(s[2*jj],   qa_l[kt2], kh);
                mma16816(s[2*jj+1], qa_h[kt2], kh + 2);
                mma16816(s[2*jj+1], qa_h[kt2], kl + 2);
                mma16816(s[2*jj+1], qa_l[kt2], kh + 2);
            }
        }

        // ---- ex2 softmax (no max-shift; scores bounded) ----
        uint32_t pa_h[4][4], pa_l[4][4];
        #pragma unroll
        for (int j = 0; j < 8; j++) {
            s[j][0] = ex2(s[j][0] + b0v[j].x);
            s[j][1] = ex2(s[j][1] + b0v[j].y);
            s[j][2] = ex2(s[j][2] + b1v[j].x);
            s[j][3] = ex2(s[j][3] + b1v[j].y);
            lsum0 += s[j][0] + s[j][1];
            lsum1 += s[j][2] + s[j][3];
        }
        #pragma unroll
        for (int u = 0; u < 4; u++) {
            split2(s[2*u][0],   s[2*u][1],   pa_h[u][0], pa_l[u][0]);
            split2(s[2*u][2],   s[2*u][3],   pa_h[u][1], pa_l[u][1]);
            split2(s[2*u+1][0], s[2*u+1][1], pa_h[u][2], pa_l[u][2]);
            split2(s[2*u+1][2], s[2*u+1][3], pa_h[u][3], pa_l[u][3]);
        }

        // ---- PV ----
        #pragma unroll
        for (int nt = 0; nt < 16; nt++) {
            uint32_t vaddr = sV + ((8 * nt + vr_part) * 72 + vc_part) * 2;
            uint32_t vh[8], vl[8];
            ldm_x4(vh,     vaddr);
            ldm_x4(vh + 4, vaddr + 64);
            ldm_x4(vl,     vaddr + 18432);
            ldm_x4(vl + 4, vaddr + 18432 + 64);
            #pragma unroll
            for (int u = 0; u < 4; u++) {
                mma16816(o[nt], pa_h[u], vh + 2 * u);
                mma16816(o[nt], pa_h[u], vl + 2 * u);
                mma16816(o[nt], pa_l[u], vh + 2 * u);
            }
        }
        __syncthreads();
        if (it + 2 < 16)
            attn_issue_stage(sb_u32, it & 1, (it + 2) * 64, bh, t);
        CP_COMMIT();
    }

    lsum0 += __shfl_xor_sync(0xffffffffu, lsum0, 1);
    lsum0 += __shfl_xor_sync(0xffffffffu, lsum0, 2);
    lsum1 += __shfl_xor_sync(0xffffffffu, lsum1, 1);
    lsum1 += __shfl_xor_sync(0xffffffffu, lsum1, 2);
    float i0 = 1.f / lsum0, i1 = 1.f / lsum1;
    #pragma unroll
    for (int nt = 0; nt < 16; nt++) {
        int col = h * VDIM + 8 * nt + 2 * tid4;
        uint32_t hh, ll;
        split2(o[nt][0] * i0, o[nt][1] * i0, hh, ll);
        size_t o0 = (size_t)(b * SEQ + r0) * OUT_DIM + col;
        *(uint32_t*)(g_aoh + o0) = hh;
        *(uint32_t*)(g_aol + o0) = ll;
        split2(o[nt][2] * i1, o[nt][3] * i1, hh, ll);
        size_t o1 = (size_t)(b * SEQ + r1) * OUT_DIM + col;
        *(uint32_t*)(g_aoh + o1) = hh;
        *(uint32_t*)(g_aol + o1) = ll;
    }
}

// ============================================================
// launch
// ============================================================
extern "C" void kernel_launch(void* const* d_in, const int* in_sizes, int n_in,
                              void* d_out, int out_size) {
    const float* x     = (const float*)d_in[0];
    const float* gamma = (const float*)d_in[1];
    const float* beta  = (const float*)d_in[2];
    const float* Wqkv  = (const float*)d_in[3];
    const float* bqkv  = (const float*)d_in[4];
    const float* Wproj = (const float*)d_in[5];
    const float* bproj = (const float*)d_in[6];
    const float* ab    = (const float*)d_in[7];
    const int*   bidx  = (const int*)d_in[8];
    float* out = (float*)d_out;

    void *pqkv, *pxh, *pxl, *pw1h, *pw1l, *pw2h, *pw2l, *paoh, *paol;
    cudaGetSymbolAddress(&pqkv, g_qkv);
    cudaGetSymbolAddress(&pxh, g_xh);   cudaGetSymbolAddress(&pxl, g_xl);
    cudaGetSymbolAddress(&pw1h, g_w1h); cudaGetSymbolAddress(&pw1l, g_w1l);
    cudaGetSymbolAddress(&pw2h, g_w2h); cudaGetSymbolAddress(&pw2l, g_w2l);
    cudaGetSymbolAddress(&paoh, g_aoh); cudaGetSymbolAddress(&paol, g_aol);

    const int gemm_smem = 40960 * 2;
    const int attn_smem = (A_OST + 2 * A_STS) * 2;   // 104448 B
    cudaFuncSetAttribute(gemm_bf_kernel,
                         cudaFuncAttributeMaxDynamicSharedMemorySize, gemm_smem);
    cudaFuncSetAttribute(attn_mma_kernel,
                         cudaFuncAttributeMaxDynamicSharedMemorySize, attn_smem);

    ln_kernel<<<MROWS, 128>>>(x, gamma, beta);
    split_w_kernel<<<(QKV_OUT * DIM / 4) / 256, 256>>>(
        Wqkv, (__nv_bfloat16*)pw1h, (__nv_bfloat16*)pw1l);
    split_w_kernel<<<(DIM * OUT_DIM / 4) / 256, 256>>>(
        Wproj, (__nv_bfloat16*)pw2h, (__nv_bfloat16*)pw2l);
    bias_pre_kernel<<<dim3(SEQ, NHEAD), 256>>>(ab, bidx);

    gemm_bf_kernel<<<dim3(MROWS / 128, QKV_OUT / 128), 256, gemm_smem>>>(
        (const __nv_bfloat16*)pxh, (const __nv_bfloat16*)pxl,
        (const __nv_bfloat16*)pw1h, (const __nv_bfloat16*)pw1l,
        bqkv, (float*)pqkv, MROWS, QKV_OUT, DIM);

    qkv_split_kernel<<<dim3(SEQ / 64, NHEAD, BATCH), 256>>>((const float*)pqkv);

    attn_mma_kernel<<<dim3(SEQ / 64, BATCH, NHEAD), 128, attn_smem>>>();

    gemm_bf_kernel<<<dim3(MROWS / 128, DIM / 128), 256, gemm_smem>>>(
        (const __nv_bfloat16*)paoh, (const __nv_bfloat16*)paol,
        (const __nv_bfloat16*)pw2h, (const __nv_bfloat16*)pw2l,
        bproj, out, MROWS, DIM, OUT_DIM);
}

// round 9
// speedup vs baseline: 1.4324x; 1.4263x over previous
#include <cuda_runtime.h>
#include <cuda_fp16.h>
#include <math.h>
#include <stdint.h>

#define BATCH   16
#define SEQ     1024
#define DIM     512
#define NHEAD   16
#define KDIM    32
#define VDIM    128
#define QKVD    192
#define QKV_OUT 3072
#define OUT_DIM 2048
#define MROWS   16384
#define ATT_SCALE 0.17677669529663687f
#define LOG2E     1.4426950408889634f

// ---------------- scratch ----------------
__device__ float  g_qkv [(size_t)MROWS * QKV_OUT];
__device__ float  g_bias[(size_t)NHEAD * SEQ * SEQ];
__device__ __half g_xh  [(size_t)MROWS * DIM];
__device__ __half g_xl  [(size_t)MROWS * DIM];
__device__ __half g_w1  [(size_t)QKV_OUT * DIM];
__device__ __half g_w2  [(size_t)DIM * OUT_DIM];
__device__ __half g_qh  [(size_t)BATCH * NHEAD * SEQ * KDIM];
__device__ __half g_ql  [(size_t)BATCH * NHEAD * SEQ * KDIM];
__device__ __half g_k   [(size_t)BATCH * NHEAD * SEQ * KDIM];
__device__ __half g_vt  [(size_t)BATCH * NHEAD * VDIM * SEQ];
__device__ __half g_aoh [(size_t)MROWS * OUT_DIM];
__device__ __half g_aol [(size_t)MROWS * OUT_DIM];

// ---------------- helpers ----------------
__device__ __forceinline__ uint32_t pack_h2(float lo, float hi) {
    uint32_t d;
    asm("cvt.rn.f16x2.f32 %0, %1, %2;" : "=r"(d) : "f"(hi), "f"(lo));
    return d;
}
__device__ __forceinline__ void split2h(float x, float y, uint32_t& hi, uint32_t& lo) {
    hi = pack_h2(x, y);
    __half2 h = *reinterpret_cast<__half2*>(&hi);
    lo = pack_h2(x - __half2float(h.x), y - __half2float(h.y));
}
__device__ __forceinline__ float ex2(float x) {
    float r;
    asm("ex2.approx.f32 %0, %1;" : "=f"(r) : "f"(x));
    return r;
}
__device__ __forceinline__ void mma16816h(float* c, const uint32_t* a, const uint32_t* b) {
    asm volatile(
        "mma.sync.aligned.m16n8k16.row.col.f32.f16.f16.f32 "
        "{%0,%1,%2,%3}, {%4,%5,%6,%7}, {%8,%9}, {%0,%1,%2,%3};"
        : "+f"(c[0]), "+f"(c[1]), "+f"(c[2]), "+f"(c[3])
        : "r"(a[0]), "r"(a[1]), "r"(a[2]), "r"(a[3]), "r"(b[0]), "r"(b[1]));
}
__device__ __forceinline__ void ldm_x4(uint32_t* r, uint32_t addr) {
    asm volatile("ldmatrix.sync.aligned.m8n8.x4.shared.b16 {%0,%1,%2,%3}, [%4];"
        : "=r"(r[0]), "=r"(r[1]), "=r"(r[2]), "=r"(r[3]) : "r"(addr));
}
__device__ __forceinline__ uint32_t smem_u32(const void* p) {
    uint32_t a;
    asm("{ .reg .u64 t; cvta.to.shared.u64 t, %1; cvt.u32.u64 %0, t; }" : "=r"(a) : "l"(p));
    return a;
}
__device__ __forceinline__ void cpa16(uint32_t dst, const void* src) {
    asm volatile("cp.async.cg.shared.global [%0], [%1], 16;" :: "r"(dst), "l"(src));
}
#define CP_COMMIT() asm volatile("cp.async.commit_group;" ::: "memory")
#define CP_WAIT1()  asm volatile("cp.async.wait_group 1;" ::: "memory")

// ============================================================
// LayerNorm -> split fp16
// ============================================================
__global__ void ln_kernel(const float* __restrict__ x,
                          const float* __restrict__ gamma,
                          const float* __restrict__ beta) {
    int row = blockIdx.x;
    int t = threadIdx.x;  // 128
    const float4* xr = reinterpret_cast<const float4*>(x + (size_t)row * DIM);
    float4 v = xr[t];
    float s = v.x + v.y + v.z + v.w;
    __shared__ float red1[4];
    __shared__ float red2[4];
    #pragma unroll
    for (int o = 16; o > 0; o >>= 1) s += __shfl_xor_sync(0xffffffffu, s, o);
    if ((t & 31) == 0) red1[t >> 5] = s;
    __syncthreads();
    float mean = (red1[0] + red1[1] + red1[2] + red1[3]) * (1.0f / DIM);
    float4 d = make_float4(v.x - mean, v.y - mean, v.z - mean, v.w - mean);
    float vs = d.x*d.x + d.y*d.y + d.z*d.z + d.w*d.w;
    #pragma unroll
    for (int o = 16; o > 0; o >>= 1) vs += __shfl_xor_sync(0xffffffffu, vs, o);
    if ((t & 31) == 0) red2[t >> 5] = vs;
    __syncthreads();
    float var = (red2[0] + red2[1] + red2[2] + red2[3]) * (1.0f / DIM);
    float rs = rsqrtf(var + 1e-5f);
    float4 g  = reinterpret_cast<const float4*>(gamma)[t];
    float4 bb = reinterpret_cast<const float4*>(beta)[t];
    float o0 = d.x * rs * g.x + bb.x;
    float o1 = d.y * rs * g.y + bb.y;
    float o2 = d.z * rs * g.z + bb.z;
    float o3 = d.w * rs * g.w + bb.w;
    uint32_t h0, l0, h1, l1;
    split2h(o0, o1, h0, l0); split2h(o2, o3, h1, l1);
    size_t base = (size_t)row * DIM + t * 4;
    *(uint2*)(g_xh + base) = make_uint2(h0, h1);
    *(uint2*)(g_xl + base) = make_uint2(l0, l1);
}

// ============================================================
// Weight -> single fp16
// ============================================================
__global__ void w_half_kernel(const float* __restrict__ w,
                              __half* __restrict__ o) {
    int i = blockIdx.x * 256 + threadIdx.x;
    float4 v = reinterpret_cast<const float4*>(w)[i];
    uint32_t h0 = pack_h2(v.x, v.y), h1 = pack_h2(v.z, v.w);
    *(uint2*)(o + (size_t)i * 4) = make_uint2(h0, h1);
}

// ============================================================
// bias pre-gather (log2e folded)
// ============================================================
__global__ void bias_pre_kernel(const float* __restrict__ ab,
                                const int* __restrict__ bidx) {
    __shared__ float tbl[SEQ];
    int q = blockIdx.x, h = blockIdx.y, t = threadIdx.x;
    #pragma unroll
    for (int i = 0; i < 4; i++) tbl[t + 256 * i] = ab[h * SEQ + t + 256 * i] * LOG2E;
    __syncthreads();
    int4 idx = *(const int4*)(bidx + (size_t)q * SEQ + 4 * t);
    float4 o = make_float4(tbl[idx.x], tbl[idx.y], tbl[idx.z], tbl[idx.w]);
    *(float4*)(g_bias + ((size_t)h * SEQ + q) * SEQ + 4 * t) = o;
}

// ============================================================
// qkv split/transpose: q -> split fp16 (scaled), k -> fp16, vT -> fp16
// ============================================================
__global__ void qkv_split_kernel(const float* __restrict__ qkv) {
    __shared__ __half sVH[128 * 72];
    int t = threadIdx.x;
    int n0 = blockIdx.x * 64, h = blockIdx.y, b = blockIdx.z;
    size_t bh = (size_t)b * NHEAD + h;
    const float QSC = ATT_SCALE * LOG2E;

    #pragma unroll
    for (int j = 0; j < 8; j++) {
        int id = t + 256 * j;
        int r = id >> 5, c = (id & 31) * 2;
        float2 v = *(const float2*)(qkv + ((size_t)((b * SEQ + n0 + r) * NHEAD + h)) * QKVD + c);
        if (c < 32) {
            uint32_t hi, lo;
            split2h(v.x * QSC, v.y * QSC, hi, lo);
            size_t o = (bh * SEQ + n0 + r) * KDIM + c;
            *(uint32_t*)(g_qh + o) = hi;
            *(uint32_t*)(g_ql + o) = lo;
        } else {
            size_t o = (bh * SEQ + n0 + r) * KDIM + (c - 32);
            *(uint32_t*)(g_k + o) = pack_h2(v.x, v.y);
        }
    }
    #pragma unroll
    for (int j = 0; j < 16; j++) {
        int id = t + 256 * j;
        int r = id >> 6, c = (id & 63) * 2;
        float2 v = *(const float2*)(qkv + ((size_t)((b * SEQ + n0 + r) * NHEAD + h)) * QKVD + 2 * KDIM + c);
        sVH[c * 72 + r]       = __float2half(v.x);
        sVH[(c + 1) * 72 + r] = __float2half(v.y);
    }
    __syncthreads();
    #pragma unroll
    for (int j = 0; j < 4; j++) {
        int id = t + 256 * j;
        int r = id >> 3, cj = (id & 7) * 8;
        size_t o = (bh * VDIM + r) * SEQ + n0 + cj;
        *(uint4*)(g_vt + o) = *(const uint4*)(sVH + r * 72 + cj);
    }
}

// ============================================================
// HMMA GEMM: C = (Ah+Al)[M,K] @ B[N,K]^T + bias. fp16 2-term,
// 128x128, BK=32, cp.async x2, ldmatrix.
// stage bytes: AH +0 | AL +10240 | B +20480 ; stride 30720
// ============================================================
__device__ __forceinline__ void gemm_issue_stage(
    uint32_t sb_u32, int stage, int kc,
    const __half* Ah, const __half* Al, const __half* B,
    int m0, int n0, int K, int t)
{
    uint32_t base = sb_u32 + stage * 30720;
    #pragma unroll
    for (int j = 0; j < 2; j++) {
        int id = t + 256 * j;
        int r = id >> 2, c = (id & 3) * 8;
        uint32_t so = (r * 40 + c) * 2;
        size_t ga = (size_t)(m0 + r) * K + kc * 32 + c;
        size_t gb = (size_t)(n0 + r) * K + kc * 32 + c;
        cpa16(base + so,         Ah + ga);
        cpa16(base + 10240 + so, Al + ga);
        cpa16(base + 20480 + so, B + gb);
    }
}

__global__ __launch_bounds__(256)
void gemm_h_kernel(const __half* __restrict__ Ah, const __half* __restrict__ Al,
                   const __half* __restrict__ B,
                   const float* __restrict__ bias, float* __restrict__ C,
                   int M, int N, int K)
{
    extern __shared__ __align__(16) char smc[];
    uint32_t sb_u32 = smem_u32(smc);

    const int t = threadIdx.x;
    const int m0 = blockIdx.x * 128, n0 = blockIdx.y * 128;
    const int lane = t & 31, warp = t >> 5;
    const int g = lane >> 2, tid4 = lane & 3;
    const int wm = warp >> 2, wn = warp & 3;

    const int ar_part = (lane & 7) + 8 * ((lane >> 3) & 1);
    const int ac_part = 8 * (lane >> 4);
    const int br_part = 8 * (lane >> 4) + (lane & 7);
    const int bc_part = 8 * ((lane >> 3) & 1);

    float acc[4][4][4];
    #pragma unroll
    for (int a = 0; a < 4; a++)
        #pragma unroll
        for (int bq = 0; bq < 4; bq++)
            #pragma unroll
            for (int e = 0; e < 4; e++) acc[a][bq][e] = 0.f;

    int nk = K >> 5;
    gemm_issue_stage(sb_u32, 0, 0, Ah, Al, B, m0, n0, K, t);
    CP_COMMIT();
    gemm_issue_stage(sb_u32, 1, 1, Ah, Al, B, m0, n0, K, t);
    CP_COMMIT();

    for (int kc = 0; kc < nk; kc++) {
        CP_WAIT1();
        __syncthreads();
        uint32_t st = sb_u32 + (kc & 1) * 30720;
        #pragma unroll
        for (int kt2 = 0; kt2 < 2; kt2++) {
            uint32_t ah[4][4], al[4][4];
            #pragma unroll
            for (int mt = 0; mt < 4; mt++) {
                uint32_t aaddr = st + ((64 * wm + 16 * mt + ar_part) * 40 + 16 * kt2 + ac_part) * 2;
                ldm_x4(ah[mt], aaddr);
                ldm_x4(al[mt], aaddr + 10240);
            }
            #pragma unroll
            for (int jj = 0; jj < 2; jj++) {
                uint32_t baddr = st + 20480 +
                    ((32 * wn + 16 * jj + br_part) * 40 + 16 * kt2 + bc_part) * 2;
                uint32_t bh[4];
                ldm_x4(bh, baddr);
                #pragma unroll
                for (int mt = 0; mt < 4; mt++) {
                    mma16816h(acc[mt][2*jj],   ah[mt], bh);
                    mma16816h(acc[mt][2*jj],   al[mt], bh);
                    mma16816h(acc[mt][2*jj+1], ah[mt], bh + 2);
                    mma16816h(acc[mt][2*jj+1], al[mt], bh + 2);
                }
            }
        }
        __syncthreads();
        if (kc + 2 < nk)
            gemm_issue_stage(sb_u32, kc & 1, kc + 2, Ah, Al, B, m0, n0, K, t);
        CP_COMMIT();
    }

    #pragma unroll
    for (int mt = 0; mt < 4; mt++) {
        int row = m0 + 64 * wm + 16 * mt + g;
        #pragma unroll
        for (int nt = 0; nt < 4; nt++) {
            int col = n0 + 32 * wn + 8 * nt + 2 * tid4;
            float2 bv = *(const float2*)(bias + col);
            float2 v0 = make_float2(acc[mt][nt][0] + bv.x, acc[mt][nt][1] + bv.y);
            float2 v1 = make_float2(acc[mt][nt][2] + bv.x, acc[mt][nt][3] + bv.y);
            *(float2*)(C + (size_t)row * N + col)       = v0;
            *(float2*)(C + (size_t)(row + 8) * N + col) = v1;
        }
    }
}

// ============================================================
// HMMA flash attention: fp16 2-term. 64 q/block, 128 thr, 4 warps,
// 2 blocks/SM. q split, k/v single fp16. ex2 softmax, no max-shift.
// smem bytes: QH 0 | QL 5120 | stage s at 10240+s*23552:
//   K +0 (64x40) | V +5120 (128x72)
// ============================================================
#define A_STS_B 23552

__device__ __forceinline__ void attn_issue_stage(
    uint32_t sb_u32, int stage, int k0, size_t bh, int t)
{
    uint32_t base = sb_u32 + 10240 + stage * A_STS_B;
    #pragma unroll
    for (int j = 0; j < 2; j++) {
        int id = t + 128 * j;
        int r = id >> 2, c = (id & 3) * 8;
        uint32_t so = (r * 40 + c) * 2;
        size_t gk = (bh * SEQ + k0 + r) * KDIM + c;
        cpa16(base + so, g_k + gk);
    }
    #pragma unroll
    for (int j = 0; j < 8; j++) {
        int id = t + 128 * j;
        int r = id >> 3, c = (id & 7) * 8;
        uint32_t so = (r * 72 + c) * 2;
        size_t gv = (bh * VDIM + r) * SEQ + k0 + c;
        cpa16(base + 5120 + so, g_vt + gv);
    }
}

__global__ __launch_bounds__(128, 2)
void attn_mma_kernel() {
    extern __shared__ __align__(16) char smc[];
    uint32_t sb_u32 = smem_u32(smc);

    const int t = threadIdx.x, lane = t & 31, warp = t >> 5;
    const int g = lane >> 2, tid4 = lane & 3;
    const int qb = blockIdx.x, b = blockIdx.y, h = blockIdx.z;
    const int q0 = qb * 64;
    const size_t bh = (size_t)b * NHEAD + h;

    const int qr_part = 16 * warp + (lane & 7) + 8 * ((lane >> 3) & 1);
    const int qc_part = 8 * (lane >> 4);
    const int kr_part = 8 * (lane >> 4) + (lane & 7);
    const int kc_part = 8 * ((lane >> 3) & 1);
    const int vr_part = lane & 7;
    const int vc_part = 8 * (lane >> 3);

    #pragma unroll
    for (int j = 0; j < 2; j++) {
        int id = t + 128 * j;
        int r = id >> 2, c = (id & 3) * 8;
        uint32_t so = (r * 40 + c) * 2;
        size_t gq = (bh * SEQ + q0 + r) * KDIM + c;
        cpa16(sb_u32 + so,        g_qh + gq);
        cpa16(sb_u32 + 5120 + so, g_ql + gq);
    }
    attn_issue_stage(sb_u32, 0, 0, bh, t);
    CP_COMMIT();
    attn_issue_stage(sb_u32, 1, 64, bh, t);
    CP_COMMIT();

    CP_WAIT1();
    __syncthreads();
    uint32_t qa_h[2][4], qa_l[2][4];
    {
        uint32_t qaddr = sb_u32 + (qr_part * 40 + qc_part) * 2;
        ldm_x4(qa_h[0], qaddr);
        ldm_x4(qa_h[1], qaddr + 32);
        ldm_x4(qa_l[0], qaddr + 5120);
        ldm_x4(qa_l[1], qaddr + 5120 + 32);
    }

    float o[16][4];
    #pragma unroll
    for (int nt = 0; nt < 16; nt++)
        #pragma unroll
        for (int e = 0; e < 4; e++) o[nt][e] = 0.f;
    float lsum0 = 0.f, lsum1 = 0.f;
    const int r0 = q0 + 16 * warp + g;
    const int r1 = r0 + 8;
    const float* bbase0 = g_bias + ((size_t)h * SEQ + r0) * SEQ + 2 * tid4;
    const float* bbase1 = g_bias + ((size_t)h * SEQ + r1) * SEQ + 2 * tid4;

    for (int it = 0; it < 16; it++) {
        CP_WAIT1();
        __syncthreads();
        const int k0 = it * 64;
        uint32_t sK = sb_u32 + 10240 + (it & 1) * A_STS_B;
        uint32_t sV = sK + 5120;

        // prefetch bias (hides LDG behind QK MMAs)
        float2 b0v[8], b1v[8];
        #pragma unroll
        for (int j = 0; j < 8; j++) {
            b0v[j] = *(const float2*)(bbase0 + k0 + 8 * j);
            b1v[j] = *(const float2*)(bbase1 + k0 + 8 * j);
        }

        // ---- QK ----
        float s[8][4];
        #pragma unroll
        for (int j = 0; j < 8; j++)
            #pragma unroll
            for (int e = 0; e < 4; e++) s[j][e] = 0.f;
        #pragma unroll
        for (int kt2 = 0; kt2 < 2; kt2++) {
            #pragma unroll
            for (int jj = 0; jj < 4; jj++) {
                uint32_t kaddr = sK + ((16 * jj + kr_part) * 40 + 16 * kt2 + kc_part) * 2;
                uint32_t kh[4];
                ldm_x4(kh, kaddr);
                mma16816h(s[2*jj],   qa_h[kt2], kh);
                mma16816h(s[2*jj],   qa_l[kt2], kh);
                mma16816h(s[2*jj+1], qa_h[kt2], kh + 2);
                mma16816h(s[2*jj+1], qa_l[kt2], kh + 2);
            }
        }

        // ---- ex2 softmax ----
        uint32_t pa_h[4][4], pa_l[4][4];
        #pragma unroll
        for (int j = 0; j < 8; j++) {
            s[j][0] = ex2(s[j][0] + b0v[j].x);
            s[j][1] = ex2(s[j][1] + b0v[j].y);
            s[j][2] = ex2(s[j][2] + b1v[j].x);
            s[j][3] = ex2(s[j][3] + b1v[j].y);
            lsum0 += s[j][0] + s[j][1];
            lsum1 += s[j][2] + s[j][3];
        }
        #pragma unroll
        for (int u = 0; u < 4; u++) {
            split2h(s[2*u][0],   s[2*u][1],   pa_h[u][0], pa_l[u][0]);
            split2h(s[2*u][2],   s[2*u][3],   pa_h[u][1], pa_l[u][1]);
            split2h(s[2*u+1][0], s[2*u+1][1], pa_h[u][2], pa_l[u][2]);
            split2h(s[2*u+1][2], s[2*u+1][3], pa_h[u][3], pa_l[u][3]);
        }

        // ---- PV ----
        #pragma unroll
        for (int nt = 0; nt < 16; nt++) {
            uint32_t vaddr = sV + ((8 * nt + vr_part) * 72 + vc_part) * 2;
            uint32_t vh[8];
            ldm_x4(vh,     vaddr);
            ldm_x4(vh + 4, vaddr + 64);
            #pragma unroll
            for (int u = 0; u < 4; u++) {
                mma16816h(o[nt], pa_h[u], vh + 2 * u);
                mma16816h(o[nt], pa_l[u], vh + 2 * u);
            }
        }
        __syncthreads();
        if (it + 2 < 16)
            attn_issue_stage(sb_u32, it & 1, (it + 2) * 64, bh, t);
        CP_COMMIT();
    }

    lsum0 += __shfl_xor_sync(0xffffffffu, lsum0, 1);
    lsum0 += __shfl_xor_sync(0xffffffffu, lsum0, 2);
    lsum1 += __shfl_xor_sync(0xffffffffu, lsum1, 1);
    lsum1 += __shfl_xor_sync(0xffffffffu, lsum1, 2);
    float i0 = 1.f / lsum0, i1 = 1.f / lsum1;
    #pragma unroll
    for (int nt = 0; nt < 16; nt++) {
        int col = h * VDIM + 8 * nt + 2 * tid4;
        uint32_t hh, ll;
        split2h(o[nt][0] * i0, o[nt][1] * i0, hh, ll);
        size_t o0 = (size_t)(b * SEQ + r0) * OUT_DIM + col;
        *(uint32_t*)(g_aoh + o0) = hh;
        *(uint32_t*)(g_aol + o0) = ll;
        split2h(o[nt][2] * i1, o[nt][3] * i1, hh, ll);
        size_t o1 = (size_t)(b * SEQ + r1) * OUT_DIM + col;
        *(uint32_t*)(g_aoh + o1) = hh;
        *(uint32_t*)(g_aol + o1) = ll;
    }
}

// ============================================================
// launch
// ============================================================
extern "C" void kernel_launch(void* const* d_in, const int* in_sizes, int n_in,
                              void* d_out, int out_size) {
    const float* x     = (const float*)d_in[0];
    const float* gamma = (const float*)d_in[1];
    const float* beta  = (const float*)d_in[2];
    const float* Wqkv  = (const float*)d_in[3];
    const float* bqkv  = (const float*)d_in[4];
    const float* Wproj = (const float*)d_in[5];
    const float* bproj = (const float*)d_in[6];
    const float* ab    = (const float*)d_in[7];
    const int*   bidx  = (const int*)d_in[8];
    float* out = (float*)d_out;

    void *pqkv, *pxh, *pxl, *pw1, *pw2, *paoh, *paol;
    cudaGetSymbolAddress(&pqkv, g_qkv);
    cudaGetSymbolAddress(&pxh, g_xh);   cudaGetSymbolAddress(&pxl, g_xl);
    cudaGetSymbolAddress(&pw1, g_w1);   cudaGetSymbolAddress(&pw2, g_w2);
    cudaGetSymbolAddress(&paoh, g_aoh); cudaGetSymbolAddress(&paol, g_aol);

    const int gemm_smem = 2 * 30720;            // 61440 B
    const int attn_smem = 10240 + 2 * A_STS_B;  // 57344 B
    cudaFuncSetAttribute(gemm_h_kernel,
                         cudaFuncAttributeMaxDynamicSharedMemorySize, gemm_smem);
    cudaFuncSetAttribute(attn_mma_kernel,
                         cudaFuncAttributeMaxDynamicSharedMemorySize, attn_smem);

    ln_kernel<<<MROWS, 128>>>(x, gamma, beta);
    w_half_kernel<<<(QKV_OUT * DIM / 4) / 256, 256>>>(Wqkv, (__half*)pw1);
    w_half_kernel<<<(DIM * OUT_DIM / 4) / 256, 256>>>(Wproj, (__half*)pw2);
    bias_pre_kernel<<<dim3(SEQ, NHEAD), 256>>>(ab, bidx);

    gemm_h_kernel<<<dim3(MROWS / 128, QKV_OUT / 128), 256, gemm_smem>>>(
        (const __half*)pxh, (const __half*)pxl, (const __half*)pw1,
        bqkv, (float*)pqkv, MROWS, QKV_OUT, DIM);

    qkv_split_kernel<<<dim3(SEQ / 64, NHEAD, BATCH), 256>>>((const float*)pqkv);

    attn_mma_kernel<<<dim3(SEQ / 64, BATCH, NHEAD), 128, attn_smem>>>();

    gemm_h_kernel<<<dim3(MROWS / 128, DIM / 128), 256, gemm_smem>>>(
        (const __half*)paoh, (const __half*)paol, (const __half*)pw2,
        bproj, out, MROWS, DIM, OUT_DIM);
}

// round 10
// speedup vs baseline: 1.6035x; 1.1195x over previous
#include <cuda_runtime.h>
#include <cuda_fp16.h>
#include <math.h>
#include <stdint.h>

#define BATCH   16
#define SEQ     1024
#define DIM     512
#define NHEAD   16
#define KDIM    32
#define VDIM    128
#define QKVD    192
#define QKV_OUT 3072
#define OUT_DIM 2048
#define MROWS   16384
#define ATT_SCALE 0.17677669529663687f
#define LOG2E     1.4426950408889634f

// ---------------- scratch ----------------
__device__ float  g_qkv [(size_t)MROWS * QKV_OUT];
__device__ float  g_bias[(size_t)NHEAD * SEQ * SEQ];
__device__ __half g_xh  [(size_t)MROWS * DIM];
__device__ __half g_xl  [(size_t)MROWS * DIM];
__device__ __half g_w1  [(size_t)QKV_OUT * DIM];
__device__ __half g_w2  [(size_t)DIM * OUT_DIM];
__device__ __half g_qh  [(size_t)BATCH * NHEAD * SEQ * KDIM];
__device__ __half g_ql  [(size_t)BATCH * NHEAD * SEQ * KDIM];
__device__ __half g_k   [(size_t)BATCH * NHEAD * SEQ * KDIM];
__device__ __half g_vt  [(size_t)BATCH * NHEAD * VDIM * SEQ];
__device__ __half g_aoh [(size_t)MROWS * OUT_DIM];
__device__ __half g_aol [(size_t)MROWS * OUT_DIM];

// ---------------- helpers ----------------
__device__ __forceinline__ uint32_t pack_h2(float lo, float hi) {
    uint32_t d;
    asm("cvt.rn.f16x2.f32 %0, %1, %2;" : "=r"(d) : "f"(hi), "f"(lo));
    return d;
}
__device__ __forceinline__ void split2h(float x, float y, uint32_t& hi, uint32_t& lo) {
    hi = pack_h2(x, y);
    __half2 h = *reinterpret_cast<__half2*>(&hi);
    lo = pack_h2(x - __half2float(h.x), y - __half2float(h.y));
}
__device__ __forceinline__ float ex2(float x) {
    float r;
    asm("ex2.approx.f32 %0, %1;" : "=f"(r) : "f"(x));
    return r;
}
__device__ __forceinline__ void mma16816h(float* c, const uint32_t* a, const uint32_t* b) {
    asm volatile(
        "mma.sync.aligned.m16n8k16.row.col.f32.f16.f16.f32 "
        "{%0,%1,%2,%3}, {%4,%5,%6,%7}, {%8,%9}, {%0,%1,%2,%3};"
        : "+f"(c[0]), "+f"(c[1]), "+f"(c[2]), "+f"(c[3])
        : "r"(a[0]), "r"(a[1]), "r"(a[2]), "r"(a[3]), "r"(b[0]), "r"(b[1]));
}
__device__ __forceinline__ void ldm_x4(uint32_t* r, uint32_t addr) {
    asm volatile("ldmatrix.sync.aligned.m8n8.x4.shared.b16 {%0,%1,%2,%3}, [%4];"
        : "=r"(r[0]), "=r"(r[1]), "=r"(r[2]), "=r"(r[3]) : "r"(addr));
}
__device__ __forceinline__ uint32_t smem_u32(const void* p) {
    uint32_t a;
    asm("{ .reg .u64 t; cvta.to.shared.u64 t, %1; cvt.u32.u64 %0, t; }" : "=r"(a) : "l"(p));
    return a;
}
__device__ __forceinline__ void cpa16(uint32_t dst, const void* src) {
    asm volatile("cp.async.cg.shared.global [%0], [%1], 16;" :: "r"(dst), "l"(src));
}
#define CP_COMMIT() asm volatile("cp.async.commit_group;" ::: "memory")
#define CP_WAIT1()  asm volatile("cp.async.wait_group 1;" ::: "memory")

// ============================================================
// LayerNorm -> split fp16
// ============================================================
__global__ void ln_kernel(const float* __restrict__ x,
                          const float* __restrict__ gamma,
                          const float* __restrict__ beta) {
    int row = blockIdx.x;
    int t = threadIdx.x;  // 128
    const float4* xr = reinterpret_cast<const float4*>(x + (size_t)row * DIM);
    float4 v = xr[t];
    float s = v.x + v.y + v.z + v.w;
    __shared__ float red1[4];
    __shared__ float red2[4];
    #pragma unroll
    for (int o = 16; o > 0; o >>= 1) s += __shfl_xor_sync(0xffffffffu, s, o);
    if ((t & 31) == 0) red1[t >> 5] = s;
    __syncthreads();
    float mean = (red1[0] + red1[1] + red1[2] + red1[3]) * (1.0f / DIM);
    float4 d = make_float4(v.x - mean, v.y - mean, v.z - mean, v.w - mean);
    float vs = d.x*d.x + d.y*d.y + d.z*d.z + d.w*d.w;
    #pragma unroll
    for (int o = 16; o > 0; o >>= 1) vs += __shfl_xor_sync(0xffffffffu, vs, o);
    if ((t & 31) == 0) red2[t >> 5] = vs;
    __syncthreads();
    float var = (red2[0] + red2[1] + red2[2] + red2[3]) * (1.0f / DIM);
    float rs = rsqrtf(var + 1e-5f);
    float4 g  = reinterpret_cast<const float4*>(gamma)[t];
    float4 bb = reinterpret_cast<const float4*>(beta)[t];
    float o0 = d.x * rs * g.x + bb.x;
    float o1 = d.y * rs * g.y + bb.y;
    float o2 = d.z * rs * g.z + bb.z;
    float o3 = d.w * rs * g.w + bb.w;
    uint32_t h0, l0, h1, l1;
    split2h(o0, o1, h0, l0); split2h(o2, o3, h1, l1);
    size_t base = (size_t)row * DIM + t * 4;
    *(uint2*)(g_xh + base) = make_uint2(h0, h1);
    *(uint2*)(g_xl + base) = make_uint2(l0, l1);
}

// ============================================================
// Weight -> single fp16
// ============================================================
__global__ void w_half_kernel(const float* __restrict__ w,
                              __half* __restrict__ o) {
    int i = blockIdx.x * 256 + threadIdx.x;
    float4 v = reinterpret_cast<const float4*>(w)[i];
    uint32_t h0 = pack_h2(v.x, v.y), h1 = pack_h2(v.z, v.w);
    *(uint2*)(o + (size_t)i * 4) = make_uint2(h0, h1);
}

// ============================================================
// bias pre-gather (log2e folded)
// ============================================================
__global__ void bias_pre_kernel(const float* __restrict__ ab,
                                const int* __restrict__ bidx) {
    __shared__ float tbl[SEQ];
    int q = blockIdx.x, h = blockIdx.y, t = threadIdx.x;
    #pragma unroll
    for (int i = 0; i < 4; i++) tbl[t + 256 * i] = ab[h * SEQ + t + 256 * i] * LOG2E;
    __syncthreads();
    int4 idx = *(const int4*)(bidx + (size_t)q * SEQ + 4 * t);
    float4 o = make_float4(tbl[idx.x], tbl[idx.y], tbl[idx.z], tbl[idx.w]);
    *(float4*)(g_bias + ((size_t)h * SEQ + q) * SEQ + 4 * t) = o;
}

// ============================================================
// qkv split/transpose: q -> split fp16 (scaled), k -> fp16, vT -> fp16
// ============================================================
__global__ void qkv_split_kernel(const float* __restrict__ qkv) {
    __shared__ __half sVH[128 * 72];
    int t = threadIdx.x;
    int n0 = blockIdx.x * 64, h = blockIdx.y, b = blockIdx.z;
    size_t bh = (size_t)b * NHEAD + h;
    const float QSC = ATT_SCALE * LOG2E;

    #pragma unroll
    for (int j = 0; j < 8; j++) {
        int id = t + 256 * j;
        int r = id >> 5, c = (id & 31) * 2;
        float2 v = *(const float2*)(qkv + ((size_t)((b * SEQ + n0 + r) * NHEAD + h)) * QKVD + c);
        if (c < 32) {
            uint32_t hi, lo;
            split2h(v.x * QSC, v.y * QSC, hi, lo);
            size_t o = (bh * SEQ + n0 + r) * KDIM + c;
            *(uint32_t*)(g_qh + o) = hi;
            *(uint32_t*)(g_ql + o) = lo;
        } else {
            size_t o = (bh * SEQ + n0 + r) * KDIM + (c - 32);
            *(uint32_t*)(g_k + o) = pack_h2(v.x, v.y);
        }
    }
    #pragma unroll
    for (int j = 0; j < 16; j++) {
        int id = t + 256 * j;
        int r = id >> 6, c = (id & 63) * 2;
        float2 v = *(const float2*)(qkv + ((size_t)((b * SEQ + n0 + r) * NHEAD + h)) * QKVD + 2 * KDIM + c);
        sVH[c * 72 + r]       = __float2half(v.x);
        sVH[(c + 1) * 72 + r] = __float2half(v.y);
    }
    __syncthreads();
    #pragma unroll
    for (int j = 0; j < 4; j++) {
        int id = t + 256 * j;
        int r = id >> 3, cj = (id & 7) * 8;
        size_t o = (bh * VDIM + r) * SEQ + n0 + cj;
        *(uint4*)(g_vt + o) = *(const uint4*)(sVH + r * 72 + cj);
    }
}

// ============================================================
// HMMA GEMM: C = (Ah+Al)[M,K] @ B[N,K]^T + bias. fp16 2-term,
// 128x128, BK=32, cp.async x2, ldmatrix.
// stage bytes: AH +0 | AL +10240 | B +20480 ; stride 30720
// ============================================================
__device__ __forceinline__ void gemm_issue_stage(
    uint32_t sb_u32, int stage, int kc,
    const __half* Ah, const __half* Al, const __half* B,
    int m0, int n0, int K, int t)
{
    uint32_t base = sb_u32 + stage * 30720;
    #pragma unroll
    for (int j = 0; j < 2; j++) {
        int id = t + 256 * j;
        int r = id >> 2, c = (id & 3) * 8;
        uint32_t so = (r * 40 + c) * 2;
        size_t ga = (size_t)(m0 + r) * K + kc * 32 + c;
        size_t gb = (size_t)(n0 + r) * K + kc * 32 + c;
        cpa16(base + so,         Ah + ga);
        cpa16(base + 10240 + so, Al + ga);
        cpa16(base + 20480 + so, B + gb);
    }
}

__global__ __launch_bounds__(256)
void gemm_h_kernel(const __half* __restrict__ Ah, const __half* __restrict__ Al,
                   const __half* __restrict__ B,
                   const float* __restrict__ bias, float* __restrict__ C,
                   int M, int N, int K)
{
    extern __shared__ __align__(16) char smc[];
    uint32_t sb_u32 = smem_u32(smc);

    const int t = threadIdx.x;
    const int m0 = blockIdx.x * 128, n0 = blockIdx.y * 128;
    const int lane = t & 31, warp = t >> 5;
    const int g = lane >> 2, tid4 = lane & 3;
    const int wm = warp >> 2, wn = warp & 3;

    const int ar_part = (lane & 7) + 8 * ((lane >> 3) & 1);
    const int ac_part = 8 * (lane >> 4);
    const int br_part = 8 * (lane >> 4) + (lane & 7);
    const int bc_part = 8 * ((lane >> 3) & 1);

    float acc[4][4][4];
    #pragma unroll
    for (int a = 0; a < 4; a++)
        #pragma unroll
        for (int bq = 0; bq < 4; bq++)
            #pragma unroll
            for (int e = 0; e < 4; e++) acc[a][bq][e] = 0.f;

    int nk = K >> 5;
    gemm_issue_stage(sb_u32, 0, 0, Ah, Al, B, m0, n0, K, t);
    CP_COMMIT();
    gemm_issue_stage(sb_u32, 1, 1, Ah, Al, B, m0, n0, K, t);
    CP_COMMIT();

    for (int kc = 0; kc < nk; kc++) {
        CP_WAIT1();
        __syncthreads();
        uint32_t st = sb_u32 + (kc & 1) * 30720;
        #pragma unroll
        for (int kt2 = 0; kt2 < 2; kt2++) {
            uint32_t ah[4][4], al[4][4];
            #pragma unroll
            for (int mt = 0; mt < 4; mt++) {
                uint32_t aaddr = st + ((64 * wm + 16 * mt + ar_part) * 40 + 16 * kt2 + ac_part) * 2;
                ldm_x4(ah[mt], aaddr);
                ldm_x4(al[mt], aaddr + 10240);
            }
            #pragma unroll
            for (int jj = 0; jj < 2; jj++) {
                uint32_t baddr = st + 20480 +
                    ((32 * wn + 16 * jj + br_part) * 40 + 16 * kt2 + bc_part) * 2;
                uint32_t bh[4];
                ldm_x4(bh, baddr);
                #pragma unroll
                for (int mt = 0; mt < 4; mt++) {
                    mma16816h(acc[mt][2*jj],   ah[mt], bh);
                    mma16816h(acc[mt][2*jj],   al[mt], bh);
                    mma16816h(acc[mt][2*jj+1], ah[mt], bh + 2);
                    mma16816h(acc[mt][2*jj+1], al[mt], bh + 2);
                }
            }
        }
        __syncthreads();
        if (kc + 2 < nk)
            gemm_issue_stage(sb_u32, kc & 1, kc + 2, Ah, Al, B, m0, n0, K, t);
        CP_COMMIT();
    }

    #pragma unroll
    for (int mt = 0; mt < 4; mt++) {
        int row = m0 + 64 * wm + 16 * mt + g;
        #pragma unroll
        for (int nt = 0; nt < 4; nt++) {
            int col = n0 + 32 * wn + 8 * nt + 2 * tid4;
            float2 bv = *(const float2*)(bias + col);
            float2 v0 = make_float2(acc[mt][nt][0] + bv.x, acc[mt][nt][1] + bv.y);
            float2 v1 = make_float2(acc[mt][nt][2] + bv.x, acc[mt][nt][3] + bv.y);
            *(float2*)(C + (size_t)row * N + col)       = v0;
            *(float2*)(C + (size_t)(row + 8) * N + col) = v1;
        }
    }
}

// ============================================================
// HMMA flash attention: fp16, q 2-term, k/v/p single-term.
// 64 q/block, 128 thr, 4 warps, 2 blocks/SM. ex2 softmax, no max.
// smem bytes: QH 0 | QL 5120 | stage s at 10240+s*23552:
//   K +0 (64x40) | V +5120 (128x72)
// ============================================================
#define A_STS_B 23552

__device__ __forceinline__ void attn_issue_stage(
    uint32_t sb_u32, int stage, int k0, size_t bh, int t)
{
    uint32_t base = sb_u32 + 10240 + stage * A_STS_B;
    #pragma unroll
    for (int j = 0; j < 2; j++) {
        int id = t + 128 * j;
        int r = id >> 2, c = (id & 3) * 8;
        uint32_t so = (r * 40 + c) * 2;
        size_t gk = (bh * SEQ + k0 + r) * KDIM + c;
        cpa16(base + so, g_k + gk);
    }
    #pragma unroll
    for (int j = 0; j < 8; j++) {
        int id = t + 128 * j;
        int r = id >> 3, c = (id & 7) * 8;
        uint32_t so = (r * 72 + c) * 2;
        size_t gv = (bh * VDIM + r) * SEQ + k0 + c;
        cpa16(base + 5120 + so, g_vt + gv);
    }
}

__global__ __launch_bounds__(128, 2)
void attn_mma_kernel() {
    extern __shared__ __align__(16) char smc[];
    uint32_t sb_u32 = smem_u32(smc);

    const int t = threadIdx.x, lane = t & 31, warp = t >> 5;
    const int g = lane >> 2, tid4 = lane & 3;
    const int qb = blockIdx.x, b = blockIdx.y, h = blockIdx.z;
    const int q0 = qb * 64;
    const size_t bh = (size_t)b * NHEAD + h;

    const int qr_part = 16 * warp + (lane & 7) + 8 * ((lane >> 3) & 1);
    const int qc_part = 8 * (lane >> 4);
    const int kr_part = 8 * (lane >> 4) + (lane & 7);
    const int kc_part = 8 * ((lane >> 3) & 1);
    const int vr_part = lane & 7;
    const int vc_part = 8 * (lane >> 3);

    #pragma unroll
    for (int j = 0; j < 2; j++) {
        int id = t + 128 * j;
        int r = id >> 2, c = (id & 3) * 8;
        uint32_t so = (r * 40 + c) * 2;
        size_t gq = (bh * SEQ + q0 + r) * KDIM + c;
        cpa16(sb_u32 + so,        g_qh + gq);
        cpa16(sb_u32 + 5120 + so, g_ql + gq);
    }
    attn_issue_stage(sb_u32, 0, 0, bh, t);
    CP_COMMIT();
    attn_issue_stage(sb_u32, 1, 64, bh, t);
    CP_COMMIT();

    CP_WAIT1();
    __syncthreads();
    uint32_t qa_h[2][4], qa_l[2][4];
    {
        uint32_t qaddr = sb_u32 + (qr_part * 40 + qc_part) * 2;
        ldm_x4(qa_h[0], qaddr);
        ldm_x4(qa_h[1], qaddr + 32);
        ldm_x4(qa_l[0], qaddr + 5120);
        ldm_x4(qa_l[1], qaddr + 5120 + 32);
    }

    float o[16][4];
    #pragma unroll
    for (int nt = 0; nt < 16; nt++)
        #pragma unroll
        for (int e = 0; e < 4; e++) o[nt][e] = 0.f;
    float lsum0 = 0.f, lsum1 = 0.f;
    const int r0 = q0 + 16 * warp + g;
    const int r1 = r0 + 8;
    const float* bbase0 = g_bias + ((size_t)h * SEQ + r0) * SEQ + 2 * tid4;
    const float* bbase1 = g_bias + ((size_t)h * SEQ + r1) * SEQ + 2 * tid4;

    for (int it = 0; it < 16; it++) {
        CP_WAIT1();
        __syncthreads();
        const int k0 = it * 64;
        uint32_t sK = sb_u32 + 10240 + (it & 1) * A_STS_B;
        uint32_t sV = sK + 5120;

        // prefetch bias (hides LDG behind QK MMAs)
        float2 b0v[8], b1v[8];
        #pragma unroll
        for (int j = 0; j < 8; j++) {
            b0v[j] = *(const float2*)(bbase0 + k0 + 8 * j);
            b1v[j] = *(const float2*)(bbase1 + k0 + 8 * j);
        }

        // ---- QK ----
        float s[8][4];
        #pragma unroll
        for (int j = 0; j < 8; j++)
            #pragma unroll
            for (int e = 0; e < 4; e++) s[j][e] = 0.f;
        #pragma unroll
        for (int kt2 = 0; kt2 < 2; kt2++) {
            #pragma unroll
            for (int jj = 0; jj < 4; jj++) {
                uint32_t kaddr = sK + ((16 * jj + kr_part) * 40 + 16 * kt2 + kc_part) * 2;
                uint32_t kh[4];
                ldm_x4(kh, kaddr);
                mma16816h(s[2*jj],   qa_h[kt2], kh);
                mma16816h(s[2*jj],   qa_l[kt2], kh);
                mma16816h(s[2*jj+1], qa_h[kt2], kh + 2);
                mma16816h(s[2*jj+1], qa_l[kt2], kh + 2);
            }
        }

        // ---- ex2 softmax (fp32 exp, single-term p pack) ----
        uint32_t pa[4][4];
        #pragma unroll
        for (int j = 0; j < 8; j++) {
            s[j][0] = ex2(s[j][0] + b0v[j].x);
            s[j][1] = ex2(s[j][1] + b0v[j].y);
            s[j][2] = ex2(s[j][2] + b1v[j].x);
            s[j][3] = ex2(s[j][3] + b1v[j].y);
            lsum0 += s[j][0] + s[j][1];
            lsum1 += s[j][2] + s[j][3];
        }
        #pragma unroll
        for (int u = 0; u < 4; u++) {
            pa[u][0] = pack_h2(s[2*u][0],   s[2*u][1]);
            pa[u][1] = pack_h2(s[2*u][2],   s[2*u][3]);
            pa[u][2] = pack_h2(s[2*u+1][0], s[2*u+1][1]);
            pa[u][3] = pack_h2(s[2*u+1][2], s[2*u+1][3]);
        }

        // ---- PV (single-term p) ----
        #pragma unroll
        for (int nt = 0; nt < 16; nt++) {
            uint32_t vaddr = sV + ((8 * nt + vr_part) * 72 + vc_part) * 2;
            uint32_t vh[8];
            ldm_x4(vh,     vaddr);
            ldm_x4(vh + 4, vaddr + 64);
            #pragma unroll
            for (int u = 0; u < 4; u++)
                mma16816h(o[nt], pa[u], vh + 2 * u);
        }
        __syncthreads();
        if (it + 2 < 16)
            attn_issue_stage(sb_u32, it & 1, (it + 2) * 64, bh, t);
        CP_COMMIT();
    }

    lsum0 += __shfl_xor_sync(0xffffffffu, lsum0, 1);
    lsum0 += __shfl_xor_sync(0xffffffffu, lsum0, 2);
    lsum1 += __shfl_xor_sync(0xffffffffu, lsum1, 1);
    lsum1 += __shfl_xor_sync(0xffffffffu, lsum1, 2);
    float i0 = 1.f / lsum0, i1 = 1.f / lsum1;
    #pragma unroll
    for (int nt = 0; nt < 16; nt++) {
        int col = h * VDIM + 8 * nt + 2 * tid4;
        uint32_t hh, ll;
        split2h(o[nt][0] * i0, o[nt][1] * i0, hh, ll);
        size_t o0 = (size_t)(b * SEQ + r0) * OUT_DIM + col;
        *(uint32_t*)(g_aoh + o0) = hh;
        *(uint32_t*)(g_aol + o0) = ll;
        split2h(o[nt][2] * i1, o[nt][3] * i1, hh, ll);
        size_t o1 = (size_t)(b * SEQ + r1) * OUT_DIM + col;
        *(uint32_t*)(g_aoh + o1) = hh;
        *(uint32_t*)(g_aol + o1) = ll;
    }
}

// ============================================================
// launch
// ============================================================
extern "C" void kernel_launch(void* const* d_in, const int* in_sizes, int n_in,
                              void* d_out, int out_size) {
    const float* x     = (const float*)d_in[0];
    const float* gamma = (const float*)d_in[1];
    const float* beta  = (const float*)d_in[2];
    const float* Wqkv  = (const float*)d_in[3];
    const float* bqkv  = (const float*)d_in[4];
    const float* Wproj = (const float*)d_in[5];
    const float* bproj = (const float*)d_in[6];
    const float* ab    = (const float*)d_in[7];
    const int*   bidx  = (const int*)d_in[8];
    float* out = (float*)d_out;

    void *pqkv, *pxh, *pxl, *pw1, *pw2, *paoh, *paol;
    cudaGetSymbolAddress(&pqkv, g_qkv);
    cudaGetSymbolAddress(&pxh, g_xh);   cudaGetSymbolAddress(&pxl, g_xl);
    cudaGetSymbolAddress(&pw1, g_w1);   cudaGetSymbolAddress(&pw2, g_w2);
    cudaGetSymbolAddress(&paoh, g_aoh); cudaGetSymbolAddress(&paol, g_aol);

    const int gemm_smem = 2 * 30720;            // 61440 B
    const int attn_smem = 10240 + 2 * A_STS_B;  // 57344 B
    cudaFuncSetAttribute(gemm_h_kernel,
                         cudaFuncAttributeMaxDynamicSharedMemorySize, gemm_smem);
    cudaFuncSetAttribute(attn_mma_kernel,
                         cudaFuncAttributeMaxDynamicSharedMemorySize, attn_smem);

    ln_kernel<<<MROWS, 128>>>(x, gamma, beta);
    w_half_kernel<<<(QKV_OUT * DIM / 4) / 256, 256>>>(Wqkv, (__half*)pw1);
    w_half_kernel<<<(DIM * OUT_DIM / 4) / 256, 256>>>(Wproj, (__half*)pw2);
    bias_pre_kernel<<<dim3(SEQ, NHEAD), 256>>>(ab, bidx);

    gemm_h_kernel<<<dim3(MROWS / 128, QKV_OUT / 128), 256, gemm_smem>>>(
        (const __half*)pxh, (const __half*)pxl, (const __half*)pw1,
        bqkv, (float*)pqkv, MROWS, QKV_OUT, DIM);

    qkv_split_kernel<<<dim3(SEQ / 64, NHEAD, BATCH), 256>>>((const float*)pqkv);

    attn_mma_kernel<<<dim3(SEQ / 64, BATCH, NHEAD), 128, attn_smem>>>();

    gemm_h_kernel<<<dim3(MROWS / 128, DIM / 128), 256, gemm_smem>>>(
        (const __half*)paoh, (const __half*)paol, (const __half*)pw2,
        bproj, out, MROWS, DIM, OUT_DIM);
}

// round 11
// speedup vs baseline: 2.0176x; 1.2582x over previous
#include <cuda_runtime.h>
#include <cuda_fp16.h>
#include <math.h>
#include <stdint.h>

#define BATCH   16
#define SEQ     1024
#define DIM     512
#define NHEAD   16
#define KDIM    32
#define VDIM    128
#define QKVD    192
#define QKV_OUT 3072
#define OUT_DIM 2048
#define MROWS   16384
#define ATT_SCALE 0.17677669529663687f
#define LOG2E     1.4426950408889634f

// ---------------- scratch ----------------
__device__ float  g_qkv [(size_t)MROWS * QKV_OUT];
__device__ float  g_bias[(size_t)NHEAD * SEQ * SEQ];
__device__ __half g_x   [(size_t)MROWS * DIM];
__device__ __half g_w1  [(size_t)QKV_OUT * DIM];
__device__ __half g_w2  [(size_t)DIM * OUT_DIM];
__device__ __half g_qh  [(size_t)BATCH * NHEAD * SEQ * KDIM];
__device__ __half g_ql  [(size_t)BATCH * NHEAD * SEQ * KDIM];
__device__ __half g_k   [(size_t)BATCH * NHEAD * SEQ * KDIM];
__device__ __half g_vt  [(size_t)BATCH * NHEAD * VDIM * SEQ];
__device__ __half g_ao  [(size_t)MROWS * OUT_DIM];

// ---------------- helpers ----------------
__device__ __forceinline__ uint32_t pack_h2(float lo, float hi) {
    uint32_t d;
    asm("cvt.rn.f16x2.f32 %0, %1, %2;" : "=r"(d) : "f"(hi), "f"(lo));
    return d;
}
__device__ __forceinline__ void split2h(float x, float y, uint32_t& hi, uint32_t& lo) {
    hi = pack_h2(x, y);
    __half2 h = *reinterpret_cast<__half2*>(&hi);
    lo = pack_h2(x - __half2float(h.x), y - __half2float(h.y));
}
__device__ __forceinline__ float ex2(float x) {
    float r;
    asm("ex2.approx.f32 %0, %1;" : "=f"(r) : "f"(x));
    return r;
}
__device__ __forceinline__ void mma16816h(float* c, const uint32_t* a, const uint32_t* b) {
    asm volatile(
        "mma.sync.aligned.m16n8k16.row.col.f32.f16.f16.f32 "
        "{%0,%1,%2,%3}, {%4,%5,%6,%7}, {%8,%9}, {%0,%1,%2,%3};"
        : "+f"(c[0]), "+f"(c[1]), "+f"(c[2]), "+f"(c[3])
        : "r"(a[0]), "r"(a[1]), "r"(a[2]), "r"(a[3]), "r"(b[0]), "r"(b[1]));
}
__device__ __forceinline__ void ldm_x4(uint32_t* r, uint32_t addr) {
    asm volatile("ldmatrix.sync.aligned.m8n8.x4.shared.b16 {%0,%1,%2,%3}, [%4];"
        : "=r"(r[0]), "=r"(r[1]), "=r"(r[2]), "=r"(r[3]) : "r"(addr));
}
__device__ __forceinline__ uint32_t smem_u32(const void* p) {
    uint32_t a;
    asm("{ .reg .u64 t; cvta.to.shared.u64 t, %1; cvt.u32.u64 %0, t; }" : "=r"(a) : "l"(p));
    return a;
}
__device__ __forceinline__ void cpa16(uint32_t dst, const void* src) {
    asm volatile("cp.async.cg.shared.global [%0], [%1], 16;" :: "r"(dst), "l"(src));
}
#define CP_COMMIT() asm volatile("cp.async.commit_group;" ::: "memory")
#define CP_WAIT2()  asm volatile("cp.async.wait_group 2;" ::: "memory")

// ============================================================
// LayerNorm -> fp16
// ============================================================
__global__ void ln_kernel(const float* __restrict__ x,
                          const float* __restrict__ gamma,
                          const float* __restrict__ beta) {
    int row = blockIdx.x;
    int t = threadIdx.x;  // 128
    const float4* xr = reinterpret_cast<const float4*>(x + (size_t)row * DIM);
    float4 v = xr[t];
    float s = v.x + v.y + v.z + v.w;
    __shared__ float red1[4];
    __shared__ float red2[4];
    #pragma unroll
    for (int o = 16; o > 0; o >>= 1) s += __shfl_xor_sync(0xffffffffu, s, o);
    if ((t & 31) == 0) red1[t >> 5] = s;
    __syncthreads();
    float mean = (red1[0] + red1[1] + red1[2] + red1[3]) * (1.0f / DIM);
    float4 d = make_float4(v.x - mean, v.y - mean, v.z - mean, v.w - mean);
    float vs = d.x*d.x + d.y*d.y + d.z*d.z + d.w*d.w;
    #pragma unroll
    for (int o = 16; o > 0; o >>= 1) vs += __shfl_xor_sync(0xffffffffu, vs, o);
    if ((t & 31) == 0) red2[t >> 5] = vs;
    __syncthreads();
    float var = (red2[0] + red2[1] + red2[2] + red2[3]) * (1.0f / DIM);
    float rs = rsqrtf(var + 1e-5f);
    float4 g  = reinterpret_cast<const float4*>(gamma)[t];
    float4 bb = reinterpret_cast<const float4*>(beta)[t];
    float o0 = d.x * rs * g.x + bb.x;
    float o1 = d.y * rs * g.y + bb.y;
    float o2 = d.z * rs * g.z + bb.z;
    float o3 = d.w * rs * g.w + bb.w;
    size_t base = (size_t)row * DIM + t * 4;
    *(uint2*)(g_x + base) = make_uint2(pack_h2(o0, o1), pack_h2(o2, o3));
}

// ============================================================
// Weight -> fp16
// ============================================================
__global__ void w_half_kernel(const float* __restrict__ w,
                              __half* __restrict__ o) {
    int i = blockIdx.x * 256 + threadIdx.x;
    float4 v = reinterpret_cast<const float4*>(w)[i];
    *(uint2*)(o + (size_t)i * 4) = make_uint2(pack_h2(v.x, v.y), pack_h2(v.z, v.w));
}

// ============================================================
// bias pre-gather (log2e folded)
// ============================================================
__global__ void bias_pre_kernel(const float* __restrict__ ab,
                                const int* __restrict__ bidx) {
    __shared__ float tbl[SEQ];
    int q = blockIdx.x, h = blockIdx.y, t = threadIdx.x;
    #pragma unroll
    for (int i = 0; i < 4; i++) tbl[t + 256 * i] = ab[h * SEQ + t + 256 * i] * LOG2E;
    __syncthreads();
    int4 idx = *(const int4*)(bidx + (size_t)q * SEQ + 4 * t);
    float4 o = make_float4(tbl[idx.x], tbl[idx.y], tbl[idx.z], tbl[idx.w]);
    *(float4*)(g_bias + ((size_t)h * SEQ + q) * SEQ + 4 * t) = o;
}

// ============================================================
// qkv split/transpose: q -> split fp16 (scaled), k -> fp16, vT -> fp16
// ============================================================
__global__ void qkv_split_kernel(const float* __restrict__ qkv) {
    __shared__ __half sVH[128 * 72];
    int t = threadIdx.x;
    int n0 = blockIdx.x * 64, h = blockIdx.y, b = blockIdx.z;
    size_t bh = (size_t)b * NHEAD + h;
    const float QSC = ATT_SCALE * LOG2E;

    #pragma unroll
    for (int j = 0; j < 8; j++) {
        int id = t + 256 * j;
        int r = id >> 5, c = (id & 31) * 2;
        float2 v = *(const float2*)(qkv + ((size_t)((b * SEQ + n0 + r) * NHEAD + h)) * QKVD + c);
        if (c < 32) {
            uint32_t hi, lo;
            split2h(v.x * QSC, v.y * QSC, hi, lo);
            size_t o = (bh * SEQ + n0 + r) * KDIM + c;
            *(uint32_t*)(g_qh + o) = hi;
            *(uint32_t*)(g_ql + o) = lo;
        } else {
            size_t o = (bh * SEQ + n0 + r) * KDIM + (c - 32);
            *(uint32_t*)(g_k + o) = pack_h2(v.x, v.y);
        }
    }
    #pragma unroll
    for (int j = 0; j < 16; j++) {
        int id = t + 256 * j;
        int r = id >> 6, c = (id & 63) * 2;
        float2 v = *(const float2*)(qkv + ((size_t)((b * SEQ + n0 + r) * NHEAD + h)) * QKVD + 2 * KDIM + c);
        sVH[c * 72 + r]       = __float2half(v.x);
        sVH[(c + 1) * 72 + r] = __float2half(v.y);
    }
    __syncthreads();
    #pragma unroll
    for (int j = 0; j < 4; j++) {
        int id = t + 256 * j;
        int r = id >> 3, cj = (id & 7) * 8;
        size_t o = (bh * VDIM + r) * SEQ + n0 + cj;
        *(uint4*)(g_vt + o) = *(const uint4*)(sVH + r * 72 + cj);
    }
}

// ============================================================
// HMMA GEMM: C = A[M,K] @ B[N,K]^T + bias, single fp16 operands,
// 128x128 tile, BK=32, 3-stage cp.async, ldmatrix.
// stage bytes: A +0 (128x40) | B +10240 ; stride 20480
// ============================================================
__device__ __forceinline__ void gemm_issue_stage(
    uint32_t sb_u32, int stage, int kc,
    const __half* A, const __half* B,
    int m0, int n0, int K, int t)
{
    uint32_t base = sb_u32 + stage * 20480;
    #pragma unroll
    for (int j = 0; j < 2; j++) {
        int id = t + 256 * j;
        int r = id >> 2, c = (id & 3) * 8;
        uint32_t so = (r * 40 + c) * 2;
        size_t ga = (size_t)(m0 + r) * K + kc * 32 + c;
        size_t gb = (size_t)(n0 + r) * K + kc * 32 + c;
        cpa16(base + so,         A + ga);
        cpa16(base + 10240 + so, B + gb);
    }
}

__global__ __launch_bounds__(256)
void gemm_h_kernel(const __half* __restrict__ A, const __half* __restrict__ B,
                   const float* __restrict__ bias, float* __restrict__ C,
                   int M, int N, int K)
{
    extern __shared__ __align__(16) char smc[];
    uint32_t sb_u32 = smem_u32(smc);

    const int t = threadIdx.x;
    const int m0 = blockIdx.x * 128, n0 = blockIdx.y * 128;
    const int lane = t & 31, warp = t >> 5;
    const int g = lane >> 2, tid4 = lane & 3;
    const int wm = warp >> 2, wn = warp & 3;

    const int ar_part = (lane & 7) + 8 * ((lane >> 3) & 1);
    const int ac_part = 8 * (lane >> 4);
    const int br_part = 8 * (lane >> 4) + (lane & 7);
    const int bc_part = 8 * ((lane >> 3) & 1);

    float acc[4][4][4];
    #pragma unroll
    for (int a = 0; a < 4; a++)
        #pragma unroll
        for (int bq = 0; bq < 4; bq++)
            #pragma unroll
            for (int e = 0; e < 4; e++) acc[a][bq][e] = 0.f;

    int nk = K >> 5;
    gemm_issue_stage(sb_u32, 0, 0, A, B, m0, n0, K, t);
    CP_COMMIT();
    gemm_issue_stage(sb_u32, 1, 1, A, B, m0, n0, K, t);
    CP_COMMIT();
    gemm_issue_stage(sb_u32, 2, 2, A, B, m0, n0, K, t);
    CP_COMMIT();

    int st_idx = 0;
    for (int kc = 0; kc < nk; kc++) {
        CP_WAIT2();
        __syncthreads();
        uint32_t st = sb_u32 + st_idx * 20480;
        #pragma unroll
        for (int kt2 = 0; kt2 < 2; kt2++) {
            uint32_t ah[4][4];
            #pragma unroll
            for (int mt = 0; mt < 4; mt++) {
                uint32_t aaddr = st + ((64 * wm + 16 * mt + ar_part) * 40 + 16 * kt2 + ac_part) * 2;
                ldm_x4(ah[mt], aaddr);
            }
            #pragma unroll
            for (int jj = 0; jj < 2; jj++) {
                uint32_t baddr = st + 10240 +
                    ((32 * wn + 16 * jj + br_part) * 40 + 16 * kt2 + bc_part) * 2;
                uint32_t bh[4];
                ldm_x4(bh, baddr);
                #pragma unroll
                for (int mt = 0; mt < 4; mt++) {
                    mma16816h(acc[mt][2*jj],   ah[mt], bh);
                    mma16816h(acc[mt][2*jj+1], ah[mt], bh + 2);
                }
            }
        }
        __syncthreads();
        if (kc + 3 < nk)
            gemm_issue_stage(sb_u32, st_idx, kc + 3, A, B, m0, n0, K, t);
        CP_COMMIT();
        st_idx = (st_idx + 1) == 3 ? 0 : (st_idx + 1);
    }

    #pragma unroll
    for (int mt = 0; mt < 4; mt++) {
        int row = m0 + 64 * wm + 16 * mt + g;
        #pragma unroll
        for (int nt = 0; nt < 4; nt++) {
            int col = n0 + 32 * wn + 8 * nt + 2 * tid4;
            float2 bv = *(const float2*)(bias + col);
            float2 v0 = make_float2(acc[mt][nt][0] + bv.x, acc[mt][nt][1] + bv.y);
            float2 v1 = make_float2(acc[mt][nt][2] + bv.x, acc[mt][nt][3] + bv.y);
            *(float2*)(C + (size_t)row * N + col)       = v0;
            *(float2*)(C + (size_t)(row + 8) * N + col) = v1;
        }
    }
}

// ============================================================
// HMMA flash attention: fp16, q 2-term, k/v/p single-term.
// 64 q/block, 128 thr, 4 warps, 2 blocks/SM, 3-stage cp.async.
// smem bytes: QH 0 | QL 5120 | stage s at 10240+s*23552:
//   K +0 (64x40) | V +5120 (128x72)
// ============================================================
#define A_STS_B 23552
#define A_NST   3

__device__ __forceinline__ void attn_issue_stage(
    uint32_t sb_u32, int stage, int k0, size_t bh, int t)
{
    uint32_t base = sb_u32 + 10240 + stage * A_STS_B;
    #pragma unroll
    for (int j = 0; j < 2; j++) {
        int id = t + 128 * j;
        int r = id >> 2, c = (id & 3) * 8;
        uint32_t so = (r * 40 + c) * 2;
        size_t gk = (bh * SEQ + k0 + r) * KDIM + c;
        cpa16(base + so, g_k + gk);
    }
    #pragma unroll
    for (int j = 0; j < 8; j++) {
        int id = t + 128 * j;
        int r = id >> 3, c = (id & 7) * 8;
        uint32_t so = (r * 72 + c) * 2;
        size_t gv = (bh * VDIM + r) * SEQ + k0 + c;
        cpa16(base + 5120 + so, g_vt + gv);
    }
}

__global__ __launch_bounds__(128, 2)
void attn_mma_kernel() {
    extern __shared__ __align__(16) char smc[];
    uint32_t sb_u32 = smem_u32(smc);

    const int t = threadIdx.x, lane = t & 31, warp = t >> 5;
    const int g = lane >> 2, tid4 = lane & 3;
    const int qb = blockIdx.x, b = blockIdx.y, h = blockIdx.z;
    const int q0 = qb * 64;
    const size_t bh = (size_t)b * NHEAD + h;

    const int qr_part = 16 * warp + (lane & 7) + 8 * ((lane >> 3) & 1);
    const int qc_part = 8 * (lane >> 4);
    const int kr_part = 8 * (lane >> 4) + (lane & 7);
    const int kc_part = 8 * ((lane >> 3) & 1);
    const int vr_part = lane & 7;
    const int vc_part = 8 * (lane >> 3);

    // stage Q (group 0, with K/V stage 0) + stages 1, 2
    #pragma unroll
    for (int j = 0; j < 2; j++) {
        int id = t + 128 * j;
        int r = id >> 2, c = (id & 3) * 8;
        uint32_t so = (r * 40 + c) * 2;
        size_t gq = (bh * SEQ + q0 + r) * KDIM + c;
        cpa16(sb_u32 + so,        g_qh + gq);
        cpa16(sb_u32 + 5120 + so, g_ql + gq);
    }
    attn_issue_stage(sb_u32, 0, 0, bh, t);
    CP_COMMIT();
    attn_issue_stage(sb_u32, 1, 64, bh, t);
    CP_COMMIT();
    attn_issue_stage(sb_u32, 2, 128, bh, t);
    CP_COMMIT();

    CP_WAIT2();
    __syncthreads();
    uint32_t qa_h[2][4], qa_l[2][4];
    {
        uint32_t qaddr = sb_u32 + (qr_part * 40 + qc_part) * 2;
        ldm_x4(qa_h[0], qaddr);
        ldm_x4(qa_h[1], qaddr + 32);
        ldm_x4(qa_l[0], qaddr + 5120);
        ldm_x4(qa_l[1], qaddr + 5120 + 32);
    }

    float o[16][4];
    #pragma unroll
    for (int nt = 0; nt < 16; nt++)
        #pragma unroll
        for (int e = 0; e < 4; e++) o[nt][e] = 0.f;
    float lsum0 = 0.f, lsum1 = 0.f;
    const int r0 = q0 + 16 * warp + g;
    const int r1 = r0 + 8;
    const float* bbase0 = g_bias + ((size_t)h * SEQ + r0) * SEQ + 2 * tid4;
    const float* bbase1 = g_bias + ((size_t)h * SEQ + r1) * SEQ + 2 * tid4;

    int st_idx = 0;
    for (int it = 0; it < 16; it++) {
        CP_WAIT2();
        __syncthreads();
        const int k0 = it * 64;
        uint32_t sK = sb_u32 + 10240 + st_idx * A_STS_B;
        uint32_t sV = sK + 5120;

        // prefetch bias (hides LDG behind QK MMAs)
        float2 b0v[8], b1v[8];
        #pragma unroll
        for (int j = 0; j < 8; j++) {
            b0v[j] = *(const float2*)(bbase0 + k0 + 8 * j);
            b1v[j] = *(const float2*)(bbase1 + k0 + 8 * j);
        }

        // ---- QK (q 2-term) ----
        float s[8][4];
        #pragma unroll
        for (int j = 0; j < 8; j++)
            #pragma unroll
            for (int e = 0; e < 4; e++) s[j][e] = 0.f;
        #pragma unroll
        for (int kt2 = 0; kt2 < 2; kt2++) {
            #pragma unroll
            for (int jj = 0; jj < 4; jj++) {
                uint32_t kaddr = sK + ((16 * jj + kr_part) * 40 + 16 * kt2 + kc_part) * 2;
                uint32_t kh[4];
                ldm_x4(kh, kaddr);
                mma16816h(s[2*jj],   qa_h[kt2], kh);
                mma16816h(s[2*jj],   qa_l[kt2], kh);
                mma16816h(s[2*jj+1], qa_h[kt2], kh + 2);
                mma16816h(s[2*jj+1], qa_l[kt2], kh + 2);
            }
        }

        // ---- ex2 softmax (fp32 exp, single-term p) ----
        uint32_t pa[4][4];
        #pragma unroll
        for (int j = 0; j < 8; j++) {
            s[j][0] = ex2(s[j][0] + b0v[j].x);
            s[j][1] = ex2(s[j][1] + b0v[j].y);
            s[j][2] = ex2(s[j][2] + b1v[j].x);
            s[j][3] = ex2(s[j][3] + b1v[j].y);
            lsum0 += s[j][0] + s[j][1];
            lsum1 += s[j][2] + s[j][3];
        }
        #pragma unroll
        for (int u = 0; u < 4; u++) {
            pa[u][0] = pack_h2(s[2*u][0],   s[2*u][1]);
            pa[u][1] = pack_h2(s[2*u][2],   s[2*u][3]);
            pa[u][2] = pack_h2(s[2*u+1][0], s[2*u+1][1]);
            pa[u][3] = pack_h2(s[2*u+1][2], s[2*u+1][3]);
        }

        // ---- PV ----
        #pragma unroll
        for (int nt = 0; nt < 16; nt++) {
            uint32_t vaddr = sV + ((8 * nt + vr_part) * 72 + vc_part) * 2;
            uint32_t vh[8];
            ldm_x4(vh,     vaddr);
            ldm_x4(vh + 4, vaddr + 64);
            #pragma unroll
            for (int u = 0; u < 4; u++)
                mma16816h(o[nt], pa[u], vh + 2 * u);
        }
        __syncthreads();
        if (it + 3 < 16)
            attn_issue_stage(sb_u32, st_idx, (it + 3) * 64, bh, t);
        CP_COMMIT();
        st_idx = (st_idx + 1) == A_NST ? 0 : (st_idx + 1);
    }

    lsum0 += __shfl_xor_sync(0xffffffffu, lsum0, 1);
    lsum0 += __shfl_xor_sync(0xffffffffu, lsum0, 2);
    lsum1 += __shfl_xor_sync(0xffffffffu, lsum1, 1);
    lsum1 += __shfl_xor_sync(0xffffffffu, lsum1, 2);
    float i0 = 1.f / lsum0, i1 = 1.f / lsum1;
    #pragma unroll
    for (int nt = 0; nt < 16; nt++) {
        int col = h * VDIM + 8 * nt + 2 * tid4;
        size_t o0 = (size_t)(b * SEQ + r0) * OUT_DIM + col;
        size_t o1 = (size_t)(b * SEQ + r1) * OUT_DIM + col;
        *(uint32_t*)(g_ao + o0) = pack_h2(o[nt][0] * i0, o[nt][1] * i0);
        *(uint32_t*)(g_ao + o1) = pack_h2(o[nt][2] * i1, o[nt][3] * i1);
    }
}

// ============================================================
// launch
// ============================================================
extern "C" void kernel_launch(void* const* d_in, const int* in_sizes, int n_in,
                              void* d_out, int out_size) {
    const float* x     = (const float*)d_in[0];
    const float* gamma = (const float*)d_in[1];
    const float* beta  = (const float*)d_in[2];
    const float* Wqkv  = (const float*)d_in[3];
    const float* bqkv  = (const float*)d_in[4];
    const float* Wproj = (const float*)d_in[5];
    const float* bproj = (const float*)d_in[6];
    const float* ab    = (const float*)d_in[7];
    const int*   bidx  = (const int*)d_in[8];
    float* out = (float*)d_out;

    void *pqkv, *px, *pw1, *pw2, *pao;
    cudaGetSymbolAddress(&pqkv, g_qkv);
    cudaGetSymbolAddress(&px, g_x);
    cudaGetSymbolAddress(&pw1, g_w1);
    cudaGetSymbolAddress(&pw2, g_w2);
    cudaGetSymbolAddress(&pao, g_ao);

    const int gemm_smem = 3 * 20480;            // 61440 B
    const int attn_smem = 10240 + A_NST * A_STS_B;  // 80896 B
    cudaFuncSetAttribute(gemm_h_kernel,
                         cudaFuncAttributeMaxDynamicSharedMemorySize, gemm_smem);
    cudaFuncSetAttribute(attn_mma_kernel,
                         cudaFuncAttributeMaxDynamicSharedMemorySize, attn_smem);

    ln_kernel<<<MROWS, 128>>>(x, gamma, beta);
    w_half_kernel<<<(QKV_OUT * DIM / 4) / 256, 256>>>(Wqkv, (__half*)pw1);
    w_half_kernel<<<(DIM * OUT_DIM / 4) / 256, 256>>>(Wproj, (__half*)pw2);
    bias_pre_kernel<<<dim3(SEQ, NHEAD), 256>>>(ab, bidx);

    gemm_h_kernel<<<dim3(MROWS / 128, QKV_OUT / 128), 256, gemm_smem>>>(
        (const __half*)px, (const __half*)pw1,
        bqkv, (float*)pqkv, MROWS, QKV_OUT, DIM);

    qkv_split_kernel<<<dim3(SEQ / 64, NHEAD, BATCH), 256>>>((const float*)pqkv);

    attn_mma_kernel<<<dim3(SEQ / 64, BATCH, NHEAD), 128, attn_smem>>>();

    gemm_h_kernel<<<dim3(MROWS / 128, DIM / 128), 256, gemm_smem>>>(
        (const __half*)pao, (const __half*)pw2,
        bproj, out, MROWS, DIM, OUT_DIM);
}

// round 12
// speedup vs baseline: 2.0502x; 1.0162x over previous
#include <cuda_runtime.h>
#include <cuda_fp16.h>
#include <math.h>
#include <stdint.h>

#define BATCH   16
#define SEQ     1024
#define DIM     512
#define NHEAD   16
#define KDIM    32
#define VDIM    128
#define QKVD    192
#define QKV_OUT 3072
#define OUT_DIM 2048
#define MROWS   16384
#define ATT_SCALE 0.17677669529663687f
#define LOG2E     1.4426950408889634f

// ---------------- scratch ----------------
__device__ float  g_qkv [(size_t)MROWS * QKV_OUT];
__device__ __half g_bias[(size_t)NHEAD * SEQ * SEQ];
__device__ __half g_x   [(size_t)MROWS * DIM];
__device__ __half g_w1  [(size_t)QKV_OUT * DIM];
__device__ __half g_w2  [(size_t)DIM * OUT_DIM];
__device__ __half g_qh  [(size_t)BATCH * NHEAD * SEQ * KDIM];
__device__ __half g_ql  [(size_t)BATCH * NHEAD * SEQ * KDIM];
__device__ __half g_k   [(size_t)BATCH * NHEAD * SEQ * KDIM];
__device__ __half g_vt  [(size_t)BATCH * NHEAD * VDIM * SEQ];
__device__ __half g_ao  [(size_t)MROWS * OUT_DIM];

// ---------------- helpers ----------------
__device__ __forceinline__ uint32_t pack_h2(float lo, float hi) {
    uint32_t d;
    asm("cvt.rn.f16x2.f32 %0, %1, %2;" : "=r"(d) : "f"(hi), "f"(lo));
    return d;
}
__device__ __forceinline__ void split2h(float x, float y, uint32_t& hi, uint32_t& lo) {
    hi = pack_h2(x, y);
    __half2 h = *reinterpret_cast<__half2*>(&hi);
    lo = pack_h2(x - __half2float(h.x), y - __half2float(h.y));
}
__device__ __forceinline__ float ex2(float x) {
    float r;
    asm("ex2.approx.f32 %0, %1;" : "=f"(r) : "f"(x));
    return r;
}
__device__ __forceinline__ void mma16816h(float* c, const uint32_t* a, const uint32_t* b) {
    asm volatile(
        "mma.sync.aligned.m16n8k16.row.col.f32.f16.f16.f32 "
        "{%0,%1,%2,%3}, {%4,%5,%6,%7}, {%8,%9}, {%0,%1,%2,%3};"
        : "+f"(c[0]), "+f"(c[1]), "+f"(c[2]), "+f"(c[3])
        : "r"(a[0]), "r"(a[1]), "r"(a[2]), "r"(a[3]), "r"(b[0]), "r"(b[1]));
}
__device__ __forceinline__ void ldm_x4(uint32_t* r, uint32_t addr) {
    asm volatile("ldmatrix.sync.aligned.m8n8.x4.shared.b16 {%0,%1,%2,%3}, [%4];"
        : "=r"(r[0]), "=r"(r[1]), "=r"(r[2]), "=r"(r[3]) : "r"(addr));
}
__device__ __forceinline__ uint32_t smem_u32(const void* p) {
    uint32_t a;
    asm("{ .reg .u64 t; cvta.to.shared.u64 t, %1; cvt.u32.u64 %0, t; }" : "=r"(a) : "l"(p));
    return a;
}
__device__ __forceinline__ void cpa16(uint32_t dst, const void* src) {
    asm volatile("cp.async.cg.shared.global [%0], [%1], 16;" :: "r"(dst), "l"(src));
}
#define CP_COMMIT() asm volatile("cp.async.commit_group;" ::: "memory")
#define CP_WAIT2()  asm volatile("cp.async.wait_group 2;" ::: "memory")
#define CP_WAIT3()  asm volatile("cp.async.wait_group 3;" ::: "memory")

// ============================================================
// LayerNorm -> fp16
// ============================================================
__global__ void ln_kernel(const float* __restrict__ x,
                          const float* __restrict__ gamma,
                          const float* __restrict__ beta) {
    int row = blockIdx.x;
    int t = threadIdx.x;  // 128
    const float4* xr = reinterpret_cast<const float4*>(x + (size_t)row * DIM);
    float4 v = xr[t];
    float s = v.x + v.y + v.z + v.w;
    __shared__ float red1[4];
    __shared__ float red2[4];
    #pragma unroll
    for (int o = 16; o > 0; o >>= 1) s += __shfl_xor_sync(0xffffffffu, s, o);
    if ((t & 31) == 0) red1[t >> 5] = s;
    __syncthreads();
    float mean = (red1[0] + red1[1] + red1[2] + red1[3]) * (1.0f / DIM);
    float4 d = make_float4(v.x - mean, v.y - mean, v.z - mean, v.w - mean);
    float vs = d.x*d.x + d.y*d.y + d.z*d.z + d.w*d.w;
    #pragma unroll
    for (int o = 16; o > 0; o >>= 1) vs += __shfl_xor_sync(0xffffffffu, vs, o);
    if ((t & 31) == 0) red2[t >> 5] = vs;
    __syncthreads();
    float var = (red2[0] + red2[1] + red2[2] + red2[3]) * (1.0f / DIM);
    float rs = rsqrtf(var + 1e-5f);
    float4 g  = reinterpret_cast<const float4*>(gamma)[t];
    float4 bb = reinterpret_cast<const float4*>(beta)[t];
    float o0 = d.x * rs * g.x + bb.x;
    float o1 = d.y * rs * g.y + bb.y;
    float o2 = d.z * rs * g.z + bb.z;
    float o3 = d.w * rs * g.w + bb.w;
    size_t base = (size_t)row * DIM + t * 4;
    *(uint2*)(g_x + base) = make_uint2(pack_h2(o0, o1), pack_h2(o2, o3));
}

// ============================================================
// Weight -> fp16
// ============================================================
__global__ void w_half_kernel(const float* __restrict__ w,
                              __half* __restrict__ o) {
    int i = blockIdx.x * 256 + threadIdx.x;
    float4 v = reinterpret_cast<const float4*>(w)[i];
    *(uint2*)(o + (size_t)i * 4) = make_uint2(pack_h2(v.x, v.y), pack_h2(v.z, v.w));
}

// ============================================================
// bias pre-gather (log2e folded, fp16 output)
// ============================================================
__global__ void bias_pre_kernel(const float* __restrict__ ab,
                                const int* __restrict__ bidx) {
    __shared__ float tbl[SEQ];
    int q = blockIdx.x, h = blockIdx.y, t = threadIdx.x;
    #pragma unroll
    for (int i = 0; i < 4; i++) tbl[t + 256 * i] = ab[h * SEQ + t + 256 * i] * LOG2E;
    __syncthreads();
    int4 idx = *(const int4*)(bidx + (size_t)q * SEQ + 4 * t);
    uint32_t p0 = pack_h2(tbl[idx.x], tbl[idx.y]);
    uint32_t p1 = pack_h2(tbl[idx.z], tbl[idx.w]);
    *(uint2*)(g_bias + ((size_t)h * SEQ + q) * SEQ + 4 * t) = make_uint2(p0, p1);
}

// ============================================================
// qkv split/transpose: q -> split fp16 (scaled), k -> fp16, vT -> fp16
// ============================================================
__global__ void qkv_split_kernel(const float* __restrict__ qkv) {
    __shared__ __half sVH[128 * 72];
    int t = threadIdx.x;
    int n0 = blockIdx.x * 64, h = blockIdx.y, b = blockIdx.z;
    size_t bh = (size_t)b * NHEAD + h;
    const float QSC = ATT_SCALE * LOG2E;

    #pragma unroll
    for (int j = 0; j < 8; j++) {
        int id = t + 256 * j;
        int r = id >> 5, c = (id & 31) * 2;
        float2 v = *(const float2*)(qkv + ((size_t)((b * SEQ + n0 + r) * NHEAD + h)) * QKVD + c);
        if (c < 32) {
            uint32_t hi, lo;
            split2h(v.x * QSC, v.y * QSC, hi, lo);
            size_t o = (bh * SEQ + n0 + r) * KDIM + c;
            *(uint32_t*)(g_qh + o) = hi;
            *(uint32_t*)(g_ql + o) = lo;
        } else {
            size_t o = (bh * SEQ + n0 + r) * KDIM + (c - 32);
            *(uint32_t*)(g_k + o) = pack_h2(v.x, v.y);
        }
    }
    #pragma unroll
    for (int j = 0; j < 16; j++) {
        int id = t + 256 * j;
        int r = id >> 6, c = (id & 63) * 2;
        float2 v = *(const float2*)(qkv + ((size_t)((b * SEQ + n0 + r) * NHEAD + h)) * QKVD + 2 * KDIM + c);
        sVH[c * 72 + r]       = __float2half(v.x);
        sVH[(c + 1) * 72 + r] = __float2half(v.y);
    }
    __syncthreads();
    #pragma unroll
    for (int j = 0; j < 4; j++) {
        int id = t + 256 * j;
        int r = id >> 3, cj = (id & 7) * 8;
        size_t o = (bh * VDIM + r) * SEQ + n0 + cj;
        *(uint4*)(g_vt + o) = *(const uint4*)(sVH + r * 72 + cj);
    }
}

// ============================================================
// HMMA GEMM: C = A[M,K] @ B[N,K]^T + bias, single fp16 operands,
// 128x128 tile, BK=32, 3-stage cp.async, ldmatrix.
// stage bytes: A +0 (128x40) | B +10240 ; stride 20480
// ============================================================
__device__ __forceinline__ void gemm_issue_stage(
    uint32_t sb_u32, int stage, int kc,
    const __half* A, const __half* B,
    int m0, int n0, int K, int t)
{
    uint32_t base = sb_u32 + stage * 20480;
    #pragma unroll
    for (int j = 0; j < 2; j++) {
        int id = t + 256 * j;
        int r = id >> 2, c = (id & 3) * 8;
        uint32_t so = (r * 40 + c) * 2;
        size_t ga = (size_t)(m0 + r) * K + kc * 32 + c;
        size_t gb = (size_t)(n0 + r) * K + kc * 32 + c;
        cpa16(base + so,         A + ga);
        cpa16(base + 10240 + so, B + gb);
    }
}

__global__ __launch_bounds__(256)
void gemm_h_kernel(const __half* __restrict__ A, const __half* __restrict__ B,
                   const float* __restrict__ bias, float* __restrict__ C,
                   int M, int N, int K)
{
    extern __shared__ __align__(16) char smc[];
    uint32_t sb_u32 = smem_u32(smc);

    const int t = threadIdx.x;
    const int m0 = blockIdx.x * 128, n0 = blockIdx.y * 128;
    const int lane = t & 31, warp = t >> 5;
    const int g = lane >> 2, tid4 = lane & 3;
    const int wm = warp >> 2, wn = warp & 3;

    const int ar_part = (lane & 7) + 8 * ((lane >> 3) & 1);
    const int ac_part = 8 * (lane >> 4);
    const int br_part = 8 * (lane >> 4) + (lane & 7);
    const int bc_part = 8 * ((lane >> 3) & 1);

    float acc[4][4][4];
    #pragma unroll
    for (int a = 0; a < 4; a++)
        #pragma unroll
        for (int bq = 0; bq < 4; bq++)
            #pragma unroll
            for (int e = 0; e < 4; e++) acc[a][bq][e] = 0.f;

    int nk = K >> 5;
    gemm_issue_stage(sb_u32, 0, 0, A, B, m0, n0, K, t);
    CP_COMMIT();
    gemm_issue_stage(sb_u32, 1, 1, A, B, m0, n0, K, t);
    CP_COMMIT();
    gemm_issue_stage(sb_u32, 2, 2, A, B, m0, n0, K, t);
    CP_COMMIT();

    int st_idx = 0;
    for (int kc = 0; kc < nk; kc++) {
        CP_WAIT2();
        __syncthreads();
        uint32_t st = sb_u32 + st_idx * 20480;
        #pragma unroll
        for (int kt2 = 0; kt2 < 2; kt2++) {
            uint32_t ah[4][4];
            #pragma unroll
            for (int mt = 0; mt < 4; mt++) {
                uint32_t aaddr = st + ((64 * wm + 16 * mt + ar_part) * 40 + 16 * kt2 + ac_part) * 2;
                ldm_x4(ah[mt], aaddr);
            }
            #pragma unroll
            for (int jj = 0; jj < 2; jj++) {
                uint32_t baddr = st + 10240 +
                    ((32 * wn + 16 * jj + br_part) * 40 + 16 * kt2 + bc_part) * 2;
                uint32_t bh[4];
                ldm_x4(bh, baddr);
                #pragma unroll
                for (int mt = 0; mt < 4; mt++) {
                    mma16816h(acc[mt][2*jj],   ah[mt], bh);
                    mma16816h(acc[mt][2*jj+1], ah[mt], bh + 2);
                }
            }
        }
        __syncthreads();
        if (kc + 3 < nk)
            gemm_issue_stage(sb_u32, st_idx, kc + 3, A, B, m0, n0, K, t);
        CP_COMMIT();
        st_idx = (st_idx + 1) == 3 ? 0 : (st_idx + 1);
    }

    #pragma unroll
    for (int mt = 0; mt < 4; mt++) {
        int row = m0 + 64 * wm + 16 * mt + g;
        #pragma unroll
        for (int nt = 0; nt < 4; nt++) {
            int col = n0 + 32 * wn + 8 * nt + 2 * tid4;
            float2 bv = *(const float2*)(bias + col);
            float2 v0 = make_float2(acc[mt][nt][0] + bv.x, acc[mt][nt][1] + bv.y);
            float2 v1 = make_float2(acc[mt][nt][2] + bv.x, acc[mt][nt][3] + bv.y);
            *(float2*)(C + (size_t)row * N + col)       = v0;
            *(float2*)(C + (size_t)(row + 8) * N + col) = v1;
        }
    }
}

// ============================================================
// HMMA flash attention: fp16, q 2-term, k/v/p single-term.
// 64 q/block, 128 thr, 4 warps, 2 blocks/SM, 4-stage cp.async,
// fp16 bias. smem bytes: QH 0 | QL 5120 | stage s at 10240+s*23552:
//   K +0 (64x40) | V +5120 (128x72)
// ============================================================
#define A_STS_B 23552
#define A_NST   4

__device__ __forceinline__ void attn_issue_stage(
    uint32_t sb_u32, int stage, int k0, size_t bh, int t)
{
    uint32_t base = sb_u32 + 10240 + stage * A_STS_B;
    #pragma unroll
    for (int j = 0; j < 2; j++) {
        int id = t + 128 * j;
        int r = id >> 2, c = (id & 3) * 8;
        uint32_t so = (r * 40 + c) * 2;
        size_t gk = (bh * SEQ + k0 + r) * KDIM + c;
        cpa16(base + so, g_k + gk);
    }
    #pragma unroll
    for (int j = 0; j < 8; j++) {
        int id = t + 128 * j;
        int r = id >> 3, c = (id & 7) * 8;
        uint32_t so = (r * 72 + c) * 2;
        size_t gv = (bh * VDIM + r) * SEQ + k0 + c;
        cpa16(base + 5120 + so, g_vt + gv);
    }
}

__global__ __launch_bounds__(128, 2)
void attn_mma_kernel() {
    extern __shared__ __align__(16) char smc[];
    uint32_t sb_u32 = smem_u32(smc);

    const int t = threadIdx.x, lane = t & 31, warp = t >> 5;
    const int g = lane >> 2, tid4 = lane & 3;
    const int qb = blockIdx.x, b = blockIdx.y, h = blockIdx.z;
    const int q0 = qb * 64;
    const size_t bh = (size_t)b * NHEAD + h;

    const int qr_part = 16 * warp + (lane & 7) + 8 * ((lane >> 3) & 1);
    const int qc_part = 8 * (lane >> 4);
    const int kr_part = 8 * (lane >> 4) + (lane & 7);
    const int kc_part = 8 * ((lane >> 3) & 1);
    const int vr_part = lane & 7;
    const int vc_part = 8 * (lane >> 3);

    // stage Q (group 0, with K/V stage 0) + stages 1..3
    #pragma unroll
    for (int j = 0; j < 2; j++) {
        int id = t + 128 * j;
        int r = id >> 2, c = (id & 3) * 8;
        uint32_t so = (r * 40 + c) * 2;
        size_t gq = (bh * SEQ + q0 + r) * KDIM + c;
        cpa16(sb_u32 + so,        g_qh + gq);
        cpa16(sb_u32 + 5120 + so, g_ql + gq);
    }
    attn_issue_stage(sb_u32, 0, 0, bh, t);
    CP_COMMIT();
    attn_issue_stage(sb_u32, 1, 64, bh, t);
    CP_COMMIT();
    attn_issue_stage(sb_u32, 2, 128, bh, t);
    CP_COMMIT();
    attn_issue_stage(sb_u32, 3, 192, bh, t);
    CP_COMMIT();

    CP_WAIT3();
    __syncthreads();
    uint32_t qa_h[2][4], qa_l[2][4];
    {
        uint32_t qaddr = sb_u32 + (qr_part * 40 + qc_part) * 2;
        ldm_x4(qa_h[0], qaddr);
        ldm_x4(qa_h[1], qaddr + 32);
        ldm_x4(qa_l[0], qaddr + 5120);
        ldm_x4(qa_l[1], qaddr + 5120 + 32);
    }

    float o[16][4];
    #pragma unroll
    for (int nt = 0; nt < 16; nt++)
        #pragma unroll
        for (int e = 0; e < 4; e++) o[nt][e] = 0.f;
    float lsum0 = 0.f, lsum1 = 0.f;
    const int r0 = q0 + 16 * warp + g;
    const int r1 = r0 + 8;
    const __half* bbase0 = g_bias + ((size_t)h * SEQ + r0) * SEQ + 2 * tid4;
    const __half* bbase1 = g_bias + ((size_t)h * SEQ + r1) * SEQ + 2 * tid4;

    int st_idx = 0;
    for (int it = 0; it < 16; it++) {
        CP_WAIT3();
        __syncthreads();
        const int k0 = it * 64;
        uint32_t sK = sb_u32 + 10240 + st_idx * A_STS_B;
        uint32_t sV = sK + 5120;

        // prefetch bias (fp16, hides LDG behind QK MMAs)
        float2 b0v[8], b1v[8];
        #pragma unroll
        for (int j = 0; j < 8; j++) {
            b0v[j] = __half22float2(*(const __half2*)(bbase0 + k0 + 8 * j));
            b1v[j] = __half22float2(*(const __half2*)(bbase1 + k0 + 8 * j));
        }

        // ---- QK (q 2-term) ----
        float s[8][4];
        #pragma unroll
        for (int j = 0; j < 8; j++)
            #pragma unroll
            for (int e = 0; e < 4; e++) s[j][e] = 0.f;
        #pragma unroll
        for (int kt2 = 0; kt2 < 2; kt2++) {
            #pragma unroll
            for (int jj = 0; jj < 4; jj++) {
                uint32_t kaddr = sK + ((16 * jj + kr_part) * 40 + 16 * kt2 + kc_part) * 2;
                uint32_t kh[4];
                ldm_x4(kh, kaddr);
                mma16816h(s[2*jj],   qa_h[kt2], kh);
                mma16816h(s[2*jj],   qa_l[kt2], kh);
                mma16816h(s[2*jj+1], qa_h[kt2], kh + 2);
                mma16816h(s[2*jj+1], qa_l[kt2], kh + 2);
            }
        }

        // ---- ex2 softmax (fp32 exp, single-term p) ----
        uint32_t pa[4][4];
        #pragma unroll
        for (int j = 0; j < 8; j++) {
            s[j][0] = ex2(s[j][0] + b0v[j].x);
            s[j][1] = ex2(s[j][1] + b0v[j].y);
            s[j][2] = ex2(s[j][2] + b1v[j].x);
            s[j][3] = ex2(s[j][3] + b1v[j].y);
            lsum0 += s[j][0] + s[j][1];
            lsum1 += s[j][2] + s[j][3];
        }
        #pragma unroll
        for (int u = 0; u < 4; u++) {
            pa[u][0] = pack_h2(s[2*u][0],   s[2*u][1]);
            pa[u][1] = pack_h2(s[2*u][2],   s[2*u][3]);
            pa[u][2] = pack_h2(s[2*u+1][0], s[2*u+1][1]);
            pa[u][3] = pack_h2(s[2*u+1][2], s[2*u+1][3]);
        }

        // ---- PV ----
        #pragma unroll
        for (int nt = 0; nt < 16; nt++) {
            uint32_t vaddr = sV + ((8 * nt + vr_part) * 72 + vc_part) * 2;
            uint32_t vh[8];
            ldm_x4(vh,     vaddr);
            ldm_x4(vh + 4, vaddr + 64);
            #pragma unroll
            for (int u = 0; u < 4; u++)
                mma16816h(o[nt], pa[u], vh + 2 * u);
        }
        __syncthreads();
        if (it + A_NST < 16)
            attn_issue_stage(sb_u32, st_idx, (it + A_NST) * 64, bh, t);
        CP_COMMIT();
        st_idx = (st_idx + 1) == A_NST ? 0 : (st_idx + 1);
    }

    lsum0 += __shfl_xor_sync(0xffffffffu, lsum0, 1);
    lsum0 += __shfl_xor_sync(0xffffffffu, lsum0, 2);
    lsum1 += __shfl_xor_sync(0xffffffffu, lsum1, 1);
    lsum1 += __shfl_xor_sync(0xffffffffu, lsum1, 2);
    float i0 = 1.f / lsum0, i1 = 1.f / lsum1;
    #pragma unroll
    for (int nt = 0; nt < 16; nt++) {
        int col = h * VDIM + 8 * nt + 2 * tid4;
        size_t o0 = (size_t)(b * SEQ + r0) * OUT_DIM + col;
        size_t o1 = (size_t)(b * SEQ + r1) * OUT_DIM + col;
        *(uint32_t*)(g_ao + o0) = pack_h2(o[nt][0] * i0, o[nt][1] * i0);
        *(uint32_t*)(g_ao + o1) = pack_h2(o[nt][2] * i1, o[nt][3] * i1);
    }
}

// ============================================================
// launch
// ============================================================
extern "C" void kernel_launch(void* const* d_in, const int* in_sizes, int n_in,
                              void* d_out, int out_size) {
    const float* x     = (const float*)d_in[0];
    const float* gamma = (const float*)d_in[1];
    const float* beta  = (const float*)d_in[2];
    const float* Wqkv  = (const float*)d_in[3];
    const float* bqkv  = (const float*)d_in[4];
    const float* Wproj = (const float*)d_in[5];
    const float* bproj = (const float*)d_in[6];
    const float* ab    = (const float*)d_in[7];
    const int*   bidx  = (const int*)d_in[8];
    float* out = (float*)d_out;

    void *pqkv, *px, *pw1, *pw2, *pao;
    cudaGetSymbolAddress(&pqkv, g_qkv);
    cudaGetSymbolAddress(&px, g_x);
    cudaGetSymbolAddress(&pw1, g_w1);
    cudaGetSymbolAddress(&pw2, g_w2);
    cudaGetSymbolAddress(&pao, g_ao);

    const int gemm_smem = 3 * 20480;                 // 61440 B
    const int attn_smem = 10240 + A_NST * A_STS_B;   // 104448 B
    cudaFuncSetAttribute(gemm_h_kernel,
                         cudaFuncAttributeMaxDynamicSharedMemorySize, gemm_smem);
    cudaFuncSetAttribute(attn_mma_kernel,
                         cudaFuncAttributeMaxDynamicSharedMemorySize, attn_smem);

    ln_kernel<<<MROWS, 128>>>(x, gamma, beta);
    w_half_kernel<<<(QKV_OUT * DIM / 4) / 256, 256>>>(Wqkv, (__half*)pw1);
    w_half_kernel<<<(DIM * OUT_DIM / 4) / 256, 256>>>(Wproj, (__half*)pw2);
    bias_pre_kernel<<<dim3(SEQ, NHEAD), 256>>>(ab, bidx);

    gemm_h_kernel<<<dim3(MROWS / 128, QKV_OUT / 128), 256, gemm_smem>>>(
        (const __half*)px, (const __half*)pw1,
        bqkv, (float*)pqkv, MROWS, QKV_OUT, DIM);

    qkv_split_kernel<<<dim3(SEQ / 64, NHEAD, BATCH), 256>>>((const float*)pqkv);

    attn_mma_kernel<<<dim3(SEQ / 64, BATCH, NHEAD), 128, attn_smem>>>();

    gemm_h_kernel<<<dim3(MROWS / 128, DIM / 128), 256, gemm_smem>>>(
        (const __half*)pao, (const __half*)pw2,
        bproj, out, MROWS, DIM, OUT_DIM);
}

// round 13
// speedup vs baseline: 2.1917x; 1.0690x over previous
#include <cuda_runtime.h>
#include <cuda_fp16.h>
#include <math.h>
#include <stdint.h>

#define BATCH   16
#define SEQ     1024
#define DIM     512
#define NHEAD   16
#define KDIM    32
#define VDIM    128
#define QKVD    192
#define QKV_OUT 3072
#define OUT_DIM 2048
#define MROWS   16384
#define ATT_SCALE 0.17677669529663687f
#define LOG2E     1.4426950408889634f

// ---------------- scratch ----------------
__device__ float  g_qkv [(size_t)MROWS * QKV_OUT];
__device__ __half g_bias[(size_t)NHEAD * SEQ * SEQ];
__device__ __half g_x   [(size_t)MROWS * DIM];
__device__ __half g_w1  [(size_t)QKV_OUT * DIM];
__device__ __half g_w2  [(size_t)DIM * OUT_DIM];
__device__ __half g_qh  [(size_t)BATCH * NHEAD * SEQ * KDIM];
__device__ __half g_ql  [(size_t)BATCH * NHEAD * SEQ * KDIM];
__device__ __half g_k   [(size_t)BATCH * NHEAD * SEQ * KDIM];
__device__ __half g_vt  [(size_t)BATCH * NHEAD * VDIM * SEQ];
__device__ __half g_ao  [(size_t)MROWS * OUT_DIM];

// ---------------- helpers ----------------
__device__ __forceinline__ uint32_t pack_h2(float lo, float hi) {
    uint32_t d;
    asm("cvt.rn.f16x2.f32 %0, %1, %2;" : "=r"(d) : "f"(hi), "f"(lo));
    return d;
}
__device__ __forceinline__ void split2h(float x, float y, uint32_t& hi, uint32_t& lo) {
    hi = pack_h2(x, y);
    __half2 h = *reinterpret_cast<__half2*>(&hi);
    lo = pack_h2(x - __half2float(h.x), y - __half2float(h.y));
}
__device__ __forceinline__ uint32_t ex2h2(uint32_t x) {
    uint32_t r;
    asm("ex2.approx.f16x2 %0, %1;" : "=r"(r) : "r"(x));
    return r;
}
__device__ __forceinline__ void mma16816h(float* c, const uint32_t* a, const uint32_t* b) {
    asm volatile(
        "mma.sync.aligned.m16n8k16.row.col.f32.f16.f16.f32 "
        "{%0,%1,%2,%3}, {%4,%5,%6,%7}, {%8,%9}, {%0,%1,%2,%3};"
        : "+f"(c[0]), "+f"(c[1]), "+f"(c[2]), "+f"(c[3])
        : "r"(a[0]), "r"(a[1]), "r"(a[2]), "r"(a[3]), "r"(b[0]), "r"(b[1]));
}
__device__ __forceinline__ void ldm_x4(uint32_t* r, uint32_t addr) {
    asm volatile("ldmatrix.sync.aligned.m8n8.x4.shared.b16 {%0,%1,%2,%3}, [%4];"
        : "=r"(r[0]), "=r"(r[1]), "=r"(r[2]), "=r"(r[3]) : "r"(addr));
}
__device__ __forceinline__ uint32_t smem_u32(const void* p) {
    uint32_t a;
    asm("{ .reg .u64 t; cvta.to.shared.u64 t, %1; cvt.u32.u64 %0, t; }" : "=r"(a) : "l"(p));
    return a;
}
__device__ __forceinline__ void cpa16(uint32_t dst, const void* src) {
    asm volatile("cp.async.cg.shared.global [%0], [%1], 16;" :: "r"(dst), "l"(src));
}
#define CP_COMMIT() asm volatile("cp.async.commit_group;" ::: "memory")
#define CP_WAIT1()  asm volatile("cp.async.wait_group 1;" ::: "memory")
#define CP_WAIT2()  asm volatile("cp.async.wait_group 2;" ::: "memory")

// ============================================================
// LayerNorm -> fp16
// ============================================================
__global__ void ln_kernel(const float* __restrict__ x,
                          const float* __restrict__ gamma,
                          const float* __restrict__ beta) {
    int row = blockIdx.x;
    int t = threadIdx.x;  // 128
    const float4* xr = reinterpret_cast<const float4*>(x + (size_t)row * DIM);
    float4 v = xr[t];
    float s = v.x + v.y + v.z + v.w;
    __shared__ float red1[4];
    __shared__ float red2[4];
    #pragma unroll
    for (int o = 16; o > 0; o >>= 1) s += __shfl_xor_sync(0xffffffffu, s, o);
    if ((t & 31) == 0) red1[t >> 5] = s;
    __syncthreads();
    float mean = (red1[0] + red1[1] + red1[2] + red1[3]) * (1.0f / DIM);
    float4 d = make_float4(v.x - mean, v.y - mean, v.z - mean, v.w - mean);
    float vs = d.x*d.x + d.y*d.y + d.z*d.z + d.w*d.w;
    #pragma unroll
    for (int o = 16; o > 0; o >>= 1) vs += __shfl_xor_sync(0xffffffffu, vs, o);
    if ((t & 31) == 0) red2[t >> 5] = vs;
    __syncthreads();
    float var = (red2[0] + red2[1] + red2[2] + red2[3]) * (1.0f / DIM);
    float rs = rsqrtf(var + 1e-5f);
    float4 g  = reinterpret_cast<const float4*>(gamma)[t];
    float4 bb = reinterpret_cast<const float4*>(beta)[t];
    float o0 = d.x * rs * g.x + bb.x;
    float o1 = d.y * rs * g.y + bb.y;
    float o2 = d.z * rs * g.z + bb.z;
    float o3 = d.w * rs * g.w + bb.w;
    size_t base = (size_t)row * DIM + t * 4;
    *(uint2*)(g_x + base) = make_uint2(pack_h2(o0, o1), pack_h2(o2, o3));
}

// ============================================================
// Weight -> fp16
// ============================================================
__global__ void w_half_kernel(const float* __restrict__ w,
                              __half* __restrict__ o) {
    int i = blockIdx.x * 256 + threadIdx.x;
    float4 v = reinterpret_cast<const float4*>(w)[i];
    *(uint2*)(o + (size_t)i * 4) = make_uint2(pack_h2(v.x, v.y), pack_h2(v.z, v.w));
}

// ============================================================
// bias pre-gather (log2e folded, fp16 output)
// ============================================================
__global__ void bias_pre_kernel(const float* __restrict__ ab,
                                const int* __restrict__ bidx) {
    __shared__ float tbl[SEQ];
    int q = blockIdx.x, h = blockIdx.y, t = threadIdx.x;
    #pragma unroll
    for (int i = 0; i < 4; i++) tbl[t + 256 * i] = ab[h * SEQ + t + 256 * i] * LOG2E;
    __syncthreads();
    int4 idx = *(const int4*)(bidx + (size_t)q * SEQ + 4 * t);
    uint32_t p0 = pack_h2(tbl[idx.x], tbl[idx.y]);
    uint32_t p1 = pack_h2(tbl[idx.z], tbl[idx.w]);
    *(uint2*)(g_bias + ((size_t)h * SEQ + q) * SEQ + 4 * t) = make_uint2(p0, p1);
}

// ============================================================
// qkv split/transpose: q -> split fp16 (scaled), k -> fp16, vT -> fp16
// ============================================================
__global__ void qkv_split_kernel(const float* __restrict__ qkv) {
    __shared__ __half sVH[128 * 72];
    int t = threadIdx.x;
    int n0 = blockIdx.x * 64, h = blockIdx.y, b = blockIdx.z;
    size_t bh = (size_t)b * NHEAD + h;
    const float QSC = ATT_SCALE * LOG2E;

    #pragma unroll
    for (int j = 0; j < 8; j++) {
        int id = t + 256 * j;
        int r = id >> 5, c = (id & 31) * 2;
        float2 v = *(const float2*)(qkv + ((size_t)((b * SEQ + n0 + r) * NHEAD + h)) * QKVD + c);
        if (c < 32) {
            uint32_t hi, lo;
            split2h(v.x * QSC, v.y * QSC, hi, lo);
            size_t o = (bh * SEQ + n0 + r) * KDIM + c;
            *(uint32_t*)(g_qh + o) = hi;
            *(uint32_t*)(g_ql + o) = lo;
        } else {
            size_t o = (bh * SEQ + n0 + r) * KDIM + (c - 32);
            *(uint32_t*)(g_k + o) = pack_h2(v.x, v.y);
        }
    }
    #pragma unroll
    for (int j = 0; j < 16; j++) {
        int id = t + 256 * j;
        int r = id >> 6, c = (id & 63) * 2;
        float2 v = *(const float2*)(qkv + ((size_t)((b * SEQ + n0 + r) * NHEAD + h)) * QKVD + 2 * KDIM + c);
        sVH[c * 72 + r]       = __float2half(v.x);
        sVH[(c + 1) * 72 + r] = __float2half(v.y);
    }
    __syncthreads();
    #pragma unroll
    for (int j = 0; j < 4; j++) {
        int id = t + 256 * j;
        int r = id >> 3, cj = (id & 7) * 8;
        size_t o = (bh * VDIM + r) * SEQ + n0 + cj;
        *(uint4*)(g_vt + o) = *(const uint4*)(sVH + r * 72 + cj);
    }
}

// ============================================================
// HMMA GEMM: C = A[M,K] @ B[N,K]^T + bias, single fp16 operands,
// 128x128 tile, BK=32, 3-stage cp.async, ldmatrix, 1 sync/iter.
// stage bytes: A +0 (128x40) | B +10240 ; stride 20480
// ============================================================
__device__ __forceinline__ void gemm_issue_stage(
    uint32_t sb_u32, int stage, int kc,
    const __half* A, const __half* B,
    int m0, int n0, int K, int t)
{
    uint32_t base = sb_u32 + stage * 20480;
    #pragma unroll
    for (int j = 0; j < 2; j++) {
        int id = t + 256 * j;
        int r = id >> 2, c = (id & 3) * 8;
        uint32_t so = (r * 40 + c) * 2;
        size_t ga = (size_t)(m0 + r) * K + kc * 32 + c;
        size_t gb = (size_t)(n0 + r) * K + kc * 32 + c;
        cpa16(base + so,         A + ga);
        cpa16(base + 10240 + so, B + gb);
    }
}

__global__ __launch_bounds__(256)
void gemm_h_kernel(const __half* __restrict__ A, const __half* __restrict__ B,
                   const float* __restrict__ bias, float* __restrict__ C,
                   int M, int N, int K)
{
    extern __shared__ __align__(16) char smc[];
    uint32_t sb_u32 = smem_u32(smc);

    const int t = threadIdx.x;
    const int m0 = blockIdx.x * 128, n0 = blockIdx.y * 128;
    const int lane = t & 31, warp = t >> 5;
    const int g = lane >> 2, tid4 = lane & 3;
    const int wm = warp >> 2, wn = warp & 3;

    const int ar_part = (lane & 7) + 8 * ((lane >> 3) & 1);
    const int ac_part = 8 * (lane >> 4);
    const int br_part = 8 * (lane >> 4) + (lane & 7);
    const int bc_part = 8 * ((lane >> 3) & 1);

    float acc[4][4][4];
    #pragma unroll
    for (int a = 0; a < 4; a++)
        #pragma unroll
        for (int bq = 0; bq < 4; bq++)
            #pragma unroll
            for (int e = 0; e < 4; e++) acc[a][bq][e] = 0.f;

    int nk = K >> 5;
    gemm_issue_stage(sb_u32, 0, 0, A, B, m0, n0, K, t);
    CP_COMMIT();
    gemm_issue_stage(sb_u32, 1, 1, A, B, m0, n0, K, t);
    CP_COMMIT();

    for (int kc = 0; kc < nk; kc++) {
        CP_WAIT1();
        __syncthreads();
        // issue stage kc+2 into buffer (kc+2)%3 = buffer consumed at kc-1 (barrier-protected)
        if (kc + 2 < nk)
            gemm_issue_stage(sb_u32, (kc + 2) % 3, kc + 2, A, B, m0, n0, K, t);
        CP_COMMIT();

        uint32_t st = sb_u32 + (kc % 3) * 20480;
        #pragma unroll
        for (int kt2 = 0; kt2 < 2; kt2++) {
            uint32_t ah[4][4];
            #pragma unroll
            for (int mt = 0; mt < 4; mt++) {
                uint32_t aaddr = st + ((64 * wm + 16 * mt + ar_part) * 40 + 16 * kt2 + ac_part) * 2;
                ldm_x4(ah[mt], aaddr);
            }
            #pragma unroll
            for (int jj = 0; jj < 2; jj++) {
                uint32_t baddr = st + 10240 +
                    ((32 * wn + 16 * jj + br_part) * 40 + 16 * kt2 + bc_part) * 2;
                uint32_t bh[4];
                ldm_x4(bh, baddr);
                #pragma unroll
                for (int mt = 0; mt < 4; mt++) {
                    mma16816h(acc[mt][2*jj],   ah[mt], bh);
                    mma16816h(acc[mt][2*jj+1], ah[mt], bh + 2);
                }
            }
        }
    }

    #pragma unroll
    for (int mt = 0; mt < 4; mt++) {
        int row = m0 + 64 * wm + 16 * mt + g;
        #pragma unroll
        for (int nt = 0; nt < 4; nt++) {
            int col = n0 + 32 * wn + 8 * nt + 2 * tid4;
            float2 bv = *(const float2*)(bias + col);
            float2 v0 = make_float2(acc[mt][nt][0] + bv.x, acc[mt][nt][1] + bv.y);
            float2 v1 = make_float2(acc[mt][nt][2] + bv.x, acc[mt][nt][3] + bv.y);
            *(float2*)(C + (size_t)row * N + col)       = v0;
            *(float2*)(C + (size_t)(row + 8) * N + col) = v1;
        }
    }
}

// ============================================================
// HMMA flash attention: fp16, q 2-term, k/v/p single-term,
// f16x2 ex2 softmax, 4-stage cp.async, ONE sync per iter.
// smem bytes: QH 0 | QL 5120 | stage s at 10240+s*23552:
//   K +0 (64x40) | V +5120 (128x72)
// ============================================================
#define A_STS_B 23552
#define A_NST   4

__device__ __forceinline__ void attn_issue_stage(
    uint32_t sb_u32, int stage, int k0, size_t bh, int t)
{
    uint32_t base = sb_u32 + 10240 + stage * A_STS_B;
    #pragma unroll
    for (int j = 0; j < 2; j++) {
        int id = t + 128 * j;
        int r = id >> 2, c = (id & 3) * 8;
        uint32_t so = (r * 40 + c) * 2;
        size_t gk = (bh * SEQ + k0 + r) * KDIM + c;
        cpa16(base + so, g_k + gk);
    }
    #pragma unroll
    for (int j = 0; j < 8; j++) {
        int id = t + 128 * j;
        int r = id >> 3, c = (id & 7) * 8;
        uint32_t so = (r * 72 + c) * 2;
        size_t gv = (bh * VDIM + r) * SEQ + k0 + c;
        cpa16(base + 5120 + so, g_vt + gv);
    }
}

__global__ __launch_bounds__(128, 2)
void attn_mma_kernel() {
    extern __shared__ __align__(16) char smc[];
    uint32_t sb_u32 = smem_u32(smc);

    const int t = threadIdx.x, lane = t & 31, warp = t >> 5;
    const int g = lane >> 2, tid4 = lane & 3;
    const int qb = blockIdx.x, b = blockIdx.y, h = blockIdx.z;
    const int q0 = qb * 64;
    const size_t bh = (size_t)b * NHEAD + h;

    const int qr_part = 16 * warp + (lane & 7) + 8 * ((lane >> 3) & 1);
    const int qc_part = 8 * (lane >> 4);
    const int kr_part = 8 * (lane >> 4) + (lane & 7);
    const int kc_part = 8 * ((lane >> 3) & 1);
    const int vr_part = lane & 7;
    const int vc_part = 8 * (lane >> 3);

    // prologue: Q + K/V stage 0 (group 0), stages 1, 2 (groups 1, 2)
    #pragma unroll
    for (int j = 0; j < 2; j++) {
        int id = t + 128 * j;
        int r = id >> 2, c = (id & 3) * 8;
        uint32_t so = (r * 40 + c) * 2;
        size_t gq = (bh * SEQ + q0 + r) * KDIM + c;
        cpa16(sb_u32 + so,        g_qh + gq);
        cpa16(sb_u32 + 5120 + so, g_ql + gq);
    }
    attn_issue_stage(sb_u32, 0, 0, bh, t);
    CP_COMMIT();
    attn_issue_stage(sb_u32, 1, 64, bh, t);
    CP_COMMIT();
    attn_issue_stage(sb_u32, 2, 128, bh, t);
    CP_COMMIT();

    CP_WAIT2();
    __syncthreads();
    uint32_t qa_h[2][4], qa_l[2][4];
    {
        uint32_t qaddr = sb_u32 + (qr_part * 40 + qc_part) * 2;
        ldm_x4(qa_h[0], qaddr);
        ldm_x4(qa_h[1], qaddr + 32);
        ldm_x4(qa_l[0], qaddr + 5120);
        ldm_x4(qa_l[1], qaddr + 5120 + 32);
    }

    float o[16][4];
    #pragma unroll
    for (int nt = 0; nt < 16; nt++)
        #pragma unroll
        for (int e = 0; e < 4; e++) o[nt][e] = 0.f;
    float lsum0 = 0.f, lsum1 = 0.f;
    const int r0 = q0 + 16 * warp + g;
    const int r1 = r0 + 8;
    const __half* bbase0 = g_bias + ((size_t)h * SEQ + r0) * SEQ + 2 * tid4;
    const __half* bbase1 = g_bias + ((size_t)h * SEQ + r1) * SEQ + 2 * tid4;

    for (int it = 0; it < 16; it++) {
        CP_WAIT2();
        __syncthreads();
        // issue stage it+3 into buffer (it+3)%4 = (it-1)%4, consumed at it-1 (barrier-protected)
        if (it + 3 < 16)
            attn_issue_stage(sb_u32, (it + 3) % A_NST, (it + 3) * 64, bh, t);
        CP_COMMIT();

        const int k0 = it * 64;
        uint32_t sK = sb_u32 + 10240 + (it % A_NST) * A_STS_B;
        uint32_t sV = sK + 5120;

        // prefetch bias (fp16)
        float2 b0v[8], b1v[8];
        #pragma unroll
        for (int j = 0; j < 8; j++) {
            b0v[j] = __half22float2(*(const __half2*)(bbase0 + k0 + 8 * j));
            b1v[j] = __half22float2(*(const __half2*)(bbase1 + k0 + 8 * j));
        }

        // ---- QK (q 2-term) ----
        float s[8][4];
        #pragma unroll
        for (int j = 0; j < 8; j++)
            #pragma unroll
            for (int e = 0; e < 4; e++) s[j][e] = 0.f;
        #pragma unroll
        for (int kt2 = 0; kt2 < 2; kt2++) {
            #pragma unroll
            for (int jj = 0; jj < 4; jj++) {
                uint32_t kaddr = sK + ((16 * jj + kr_part) * 40 + 16 * kt2 + kc_part) * 2;
                uint32_t kh[4];
                ldm_x4(kh, kaddr);
                mma16816h(s[2*jj],   qa_h[kt2], kh);
                mma16816h(s[2*jj],   qa_l[kt2], kh);
                mma16816h(s[2*jj+1], qa_h[kt2], kh + 2);
                mma16816h(s[2*jj+1], qa_l[kt2], kh + 2);
            }
        }

        // ---- f16x2 ex2 softmax (p emerges directly in fp16) ----
        uint32_t pa[4][4];
        #pragma unroll
        for (int j = 0; j < 8; j++) {
            uint32_t e01 = ex2h2(pack_h2(s[j][0] + b0v[j].x, s[j][1] + b0v[j].y));
            uint32_t e23 = ex2h2(pack_h2(s[j][2] + b1v[j].x, s[j][3] + b1v[j].y));
            pa[j >> 1][(j & 1) * 2 + 0] = e01;
            pa[j >> 1][(j & 1) * 2 + 1] = e23;
            float2 f01 = __half22float2(*reinterpret_cast<__half2*>(&e01));
            float2 f23 = __half22float2(*reinterpret_cast<__half2*>(&e23));
            lsum0 += f01.x + f01.y;
            lsum1 += f23.x + f23.y;
        }

        // ---- PV ----
        #pragma unroll
        for (int nt = 0; nt < 16; nt++) {
            uint32_t vaddr = sV + ((8 * nt + vr_part) * 72 + vc_part) * 2;
            uint32_t vh[8];
            ldm_x4(vh,     vaddr);
            ldm_x4(vh + 4, vaddr + 64);
            #pragma unroll
            for (int u = 0; u < 4; u++)
                mma16816h(o[nt], pa[u], vh + 2 * u);
        }
    }

    lsum0 += __shfl_xor_sync(0xffffffffu, lsum0, 1);
    lsum0 += __shfl_xor_sync(0xffffffffu, lsum0, 2);
    lsum1 += __shfl_xor_sync(0xffffffffu, lsum1, 1);
    lsum1 += __shfl_xor_sync(0xffffffffu, lsum1, 2);
    float i0 = 1.f / lsum0, i1 = 1.f / lsum1;
    #pragma unroll
    for (int nt = 0; nt < 16; nt++) {
        int col = h * VDIM + 8 * nt + 2 * tid4;
        size_t o0 = (size_t)(b * SEQ + r0) * OUT_DIM + col;
        size_t o1 = (size_t)(b * SEQ + r1) * OUT_DIM + col;
        *(uint32_t*)(g_ao + o0) = pack_h2(o[nt][0] * i0, o[nt][1] * i0);
        *(uint32_t*)(g_ao + o1) = pack_h2(o[nt][2] * i1, o[nt][3] * i1);
    }
}

// ============================================================
// launch
// ============================================================
extern "C" void kernel_launch(void* const* d_in, const int* in_sizes, int n_in,
                              void* d_out, int out_size) {
    const float* x     = (const float*)d_in[0];
    const float* gamma = (const float*)d_in[1];
    const float* beta  = (const float*)d_in[2];
    const float* Wqkv  = (const float*)d_in[3];
    const float* bqkv  = (const float*)d_in[4];
    const float* Wproj = (const float*)d_in[5];
    const float* bproj = (const float*)d_in[6];
    const float* ab    = (const float*)d_in[7];
    const int*   bidx  = (const int*)d_in[8];
    float* out = (float*)d_out;

    void *pqkv, *px, *pw1, *pw2, *pao;
    cudaGetSymbolAddress(&pqkv, g_qkv);
    cudaGetSymbolAddress(&px, g_x);
    cudaGetSymbolAddress(&pw1, g_w1);
    cudaGetSymbolAddress(&pw2, g_w2);
    cudaGetSymbolAddress(&pao, g_ao);

    const int gemm_smem = 3 * 20480;                 // 61440 B
    const int attn_smem = 10240 + A_NST * A_STS_B;   // 104448 B
    cudaFuncSetAttribute(gemm_h_kernel,
                         cudaFuncAttributeMaxDynamicSharedMemorySize, gemm_smem);
    cudaFuncSetAttribute(attn_mma_kernel,
                         cudaFuncAttributeMaxDynamicSharedMemorySize, attn_smem);

    ln_kernel<<<MROWS, 128>>>(x, gamma, beta);
    w_half_kernel<<<(QKV_OUT * DIM / 4) / 256, 256>>>(Wqkv, (__half*)pw1);
    w_half_kernel<<<(DIM * OUT_DIM / 4) / 256, 256>>>(Wproj, (__half*)pw2);
    bias_pre_kernel<<<dim3(SEQ, NHEAD), 256>>>(ab, bidx);

    gemm_h_kernel<<<dim3(MROWS / 128, QKV_OUT / 128), 256, gemm_smem>>>(
        (const __half*)px, (const __half*)pw1,
        bqkv, (float*)pqkv, MROWS, QKV_OUT, DIM);

    qkv_split_kernel<<<dim3(SEQ / 64, NHEAD, BATCH), 256>>>((const float*)pqkv);

    attn_mma_kernel<<<dim3(SEQ / 64, BATCH, NHEAD), 128, attn_smem>>>();

    gemm_h_kernel<<<dim3(MROWS / 128, DIM / 128), 256, gemm_smem>>>(
        (const __half*)pao, (const __half*)pw2,
        bproj, out, MROWS, DIM, OUT_DIM);
}